// round 9
// baseline (speedup 1.0000x reference)
#include <cuda_runtime.h>
#include <cuda_bf16.h>
#include <math.h>
#include <stdint.h>

// Problem constants
#define Bb 2
#define Nn 256
#define Dd 256
#define Ee 256
#define SZ_NODES (Bb*Nn*Dd)            // 131072
#define SZ_EDGES ((size_t)Bb*Nn*Nn*Ee) // 33554432
#define M_EDGE   (Bb*Nn*Nn)            // 131072

// ======================= helpers =======================
__device__ __forceinline__ uint32_t smem_to_u32(const void* smem_ptr) {
    uint32_t addr;
    asm("{ .reg .u64 tmp; cvta.to.shared.u64 tmp, %1; cvt.u32.u64 %0, tmp; }"
        : "=r"(addr) : "l"(smem_ptr));
    return addr;
}
__device__ __forceinline__ float tf32r(float x) {
    uint32_t u;
    asm("cvt.rna.tf32.f32 %0, %1;" : "=r"(u) : "f"(x));
    return __uint_as_float(u);
}
__device__ __forceinline__ void cp16(uint32_t dst, const void* src) {
    asm volatile("cp.async.cg.shared.global [%0], [%1], 16;" :: "r"(dst), "l"(src));
}
__device__ __forceinline__ void cp_commit() {
    asm volatile("cp.async.commit_group;");
}
template<int NMAX>
__device__ __forceinline__ void cp_wait() {
    asm volatile("cp.async.wait_group %0;" :: "n"(NMAX));
}
__device__ __forceinline__ void mma_tf32(float* d, const uint32_t* a, const uint32_t* b) {
    asm volatile(
        "mma.sync.aligned.m16n8k8.row.col.f32.tf32.tf32.f32 "
        "{%0,%1,%2,%3},{%4,%5,%6,%7},{%8,%9},{%0,%1,%2,%3};"
        : "+f"(d[0]), "+f"(d[1]), "+f"(d[2]), "+f"(d[3])
        : "r"(a[0]), "r"(a[1]), "r"(a[2]), "r"(a[3]), "r"(b[0]), "r"(b[1]));
}

// ======================= scratch (static device memory) =======================
__device__ float g_X  [512*256];
__device__ float g_qkv[512*768];
__device__ float g_wv [512*256];
__device__ float g_n1 [512*256];
__device__ float g_nA [512*256];
__device__ float g_nh [512*1024];
__device__ float g_no [512*256];

__device__ float g_T  [(size_t)M_EDGE*256];   // exact LN1 output
__device__ float g_Tr [(size_t)M_EDGE*256];   // tf32-rounded copy
__device__ float g_Weor[256*256];
__device__ float g_We1r[1024*256];
__device__ float g_We2r[256*1024];

// ======================= small kernels =======================
__global__ void x_kernel(const float* __restrict__ nodes,
                         const float* __restrict__ conds,
                         float* __restrict__ X)
{
    int idx = blockIdx.x * 256 + threadIdx.x;
    int b = idx >> 16;
    int d = idx & 255;
    X[idx] = nodes[idx] + conds[b * 256 + d];
}

__global__ void wround_kernel(const float* __restrict__ s, float* __restrict__ d, int n)
{
    int i = blockIdx.x * 256 + threadIdx.x;
    if (i < n) d[i] = tf32r(s[i]);
}

// ---------------- fp32 SGEMM for the (small) node path ----------------
template<bool RELU>
__global__ __launch_bounds__(256, 2)
void sgemm_kernel(const float* __restrict__ A, const float* __restrict__ W,
                  const float* __restrict__ bias, float* __restrict__ C,
                  int M, int N, int K)
{
    __shared__ float As[16][128];
    __shared__ float Ws[16][128];
    const int tid  = threadIdx.x;
    const int tx   = tid & 15;
    const int ty   = tid >> 4;
    const int lrow = tid >> 2;
    const int lcol = (tid & 3) << 2;
    const float* Ab = A + (size_t)blockIdx.y * 128 * K;
    const float* Wb = W + (size_t)blockIdx.x * 128 * K;
    float acc[8][8];
#pragma unroll
    for (int r = 0; r < 8; r++)
#pragma unroll
        for (int c = 0; c < 8; c++) acc[r][c] = 0.f;
    for (int k0 = 0; k0 < K; k0 += 16) {
        float4 a0 = *(const float4*)(Ab + (size_t)lrow        * K + k0 + lcol);
        float4 a1 = *(const float4*)(Ab + (size_t)(lrow + 64) * K + k0 + lcol);
        float4 w0 = *(const float4*)(Wb + (size_t)lrow        * K + k0 + lcol);
        float4 w1 = *(const float4*)(Wb + (size_t)(lrow + 64) * K + k0 + lcol);
        __syncthreads();
        As[lcol+0][lrow]    = a0.x; As[lcol+1][lrow]    = a0.y;
        As[lcol+2][lrow]    = a0.z; As[lcol+3][lrow]    = a0.w;
        As[lcol+0][lrow+64] = a1.x; As[lcol+1][lrow+64] = a1.y;
        As[lcol+2][lrow+64] = a1.z; As[lcol+3][lrow+64] = a1.w;
        Ws[lcol+0][lrow]    = w0.x; Ws[lcol+1][lrow]    = w0.y;
        Ws[lcol+2][lrow]    = w0.z; Ws[lcol+3][lrow]    = w0.w;
        Ws[lcol+0][lrow+64] = w1.x; Ws[lcol+1][lrow+64] = w1.y;
        Ws[lcol+2][lrow+64] = w1.z; Ws[lcol+3][lrow+64] = w1.w;
        __syncthreads();
#pragma unroll
        for (int kk = 0; kk < 16; kk++) {
            float a[8], wv[8];
            *(float4*)(a)      = *(const float4*)&As[kk][ty * 4];
            *(float4*)(a + 4)  = *(const float4*)&As[kk][64 + ty * 4];
            *(float4*)(wv)     = *(const float4*)&Ws[kk][tx * 4];
            *(float4*)(wv + 4) = *(const float4*)&Ws[kk][64 + tx * 4];
#pragma unroll
            for (int r = 0; r < 8; r++)
#pragma unroll
                for (int c = 0; c < 8; c++) acc[r][c] += a[r] * wv[c];
        }
    }
    float bv[8];
#pragma unroll
    for (int c = 0; c < 8; c++) {
        int n = blockIdx.x * 128 + ((c < 4) ? (tx * 4 + c) : (64 + tx * 4 + (c - 4)));
        bv[c] = bias[n];
    }
#pragma unroll
    for (int r = 0; r < 8; r++) {
        int row = blockIdx.y * 128 + ((r < 4) ? (ty * 4 + r) : (64 + ty * 4 + (r - 4)));
        float4 o0, o1; float v;
        v = acc[r][0] + bv[0]; if (RELU) v = fmaxf(v, 0.f); o0.x = v;
        v = acc[r][1] + bv[1]; if (RELU) v = fmaxf(v, 0.f); o0.y = v;
        v = acc[r][2] + bv[2]; if (RELU) v = fmaxf(v, 0.f); o0.z = v;
        v = acc[r][3] + bv[3]; if (RELU) v = fmaxf(v, 0.f); o0.w = v;
        v = acc[r][4] + bv[4]; if (RELU) v = fmaxf(v, 0.f); o1.x = v;
        v = acc[r][5] + bv[5]; if (RELU) v = fmaxf(v, 0.f); o1.y = v;
        v = acc[r][6] + bv[6]; if (RELU) v = fmaxf(v, 0.f); o1.z = v;
        v = acc[r][7] + bv[7]; if (RELU) v = fmaxf(v, 0.f); o1.w = v;
        float* Crow = C + (size_t)row * N + blockIdx.x * 128;
        *(float4*)(Crow + tx * 4)      = o0;
        *(float4*)(Crow + 64 + tx * 4) = o1;
    }
}

// ---------------- attention ----------------
__global__ __launch_bounds__(256)
void attn_kernel(const float* __restrict__ qkv, const float* __restrict__ edges,
                 float* __restrict__ wv)
{
    int i = blockIdx.x, h = blockIdx.y, b = blockIdx.z;
    __shared__ __align__(16) float q[32];
    __shared__ float p[256];
    __shared__ float red[256];
    __shared__ float pv[8][32];
    int tid = threadIdx.x;
    if (tid < 32) q[tid] = qkv[((size_t)(b * 256 + i)) * 768 + h * 32 + tid];
    __syncthreads();
    int j = tid;
    const float4* k4 = (const float4*)(qkv + ((size_t)(b * 256 + j)) * 768 + 256 + h * 32);
    const float4* e4 = (const float4*)(edges + (((size_t)(b * 256 + i)) * 256 + j) * 256 + h * 32);
    float dot = 0.f, es = 0.f;
#pragma unroll
    for (int d4 = 0; d4 < 8; d4++) {
        float4 kv = k4[d4]; float4 ev = e4[d4];
        float4 qv = *(const float4*)&q[d4 * 4];
        dot += qv.x * kv.x + qv.y * kv.y + qv.z * kv.z + qv.w * kv.w;
        es  += ev.x + ev.y + ev.z + ev.w;
    }
    float logit = dot * 0.0625f + es;
    red[tid] = logit; __syncthreads();
    for (int s = 128; s > 0; s >>= 1) {
        if (tid < s) red[tid] = fmaxf(red[tid], red[tid + s]);
        __syncthreads();
    }
    float mx = red[0];
    __syncthreads();
    float e = expf(logit - mx);
    p[tid] = e; red[tid] = e; __syncthreads();
    for (int s = 128; s > 0; s >>= 1) {
        if (tid < s) red[tid] += red[tid + s];
        __syncthreads();
    }
    float inv = 1.f / red[0];
    int d = tid & 31, g = tid >> 5;
    float acc = 0.f;
    for (int jj = g * 32; jj < g * 32 + 32; jj++)
        acc += p[jj] * qkv[((size_t)(b * 256 + jj)) * 768 + 512 + h * 32 + d];
    pv[g][d] = acc;
    __syncthreads();
    if (tid < 32) {
        float s = 0.f;
#pragma unroll
        for (int g2 = 0; g2 < 8; g2++) s += pv[g2][tid];
        wv[((size_t)(b * 256 + i)) * 256 + h * 32 + tid] = s * inv;
    }
}

// ---------------- LayerNorm (node path only) ----------------
__global__ __launch_bounds__(256)
void ln_kernel(const float* __restrict__ x, const float* __restrict__ resid,
               const float* __restrict__ g, const float* __restrict__ bb,
               float* __restrict__ out)
{
    __shared__ float s1[256];
    __shared__ float s2[256];
    size_t row = blockIdx.x;
    int t = threadIdx.x;
    float v = x[row * 256 + t] + resid[row * 256 + t];
    s1[t] = v; s2[t] = v * v;
    __syncthreads();
    for (int s = 128; s > 0; s >>= 1) {
        if (t < s) { s1[t] += s1[t + s]; s2[t] += s2[t + s]; }
        __syncthreads();
    }
    float mean = s1[0] * (1.f / 256.f);
    float var  = s2[0] * (1.f / 256.f) - mean * mean;
    float inv  = rsqrtf(var + 1e-5f);
    out[row * 256 + t] = (v - mean) * inv * g[t] + bb[t];
}

__global__ void copy_conds(const float* __restrict__ c, float* __restrict__ o)
{
    o[threadIdx.x] = c[threadIdx.x];
}

// ======================= GEMM1: fused buildR + GEMM + LN1 (unchanged from R6) =======================
#define TC_SMEM (4096 + 2*49152)

__global__ __launch_bounds__(256)
void gemm1_kernel(const float* __restrict__ edges, const float* __restrict__ W,
                  const float* __restrict__ bias,
                  const float* __restrict__ gam, const float* __restrict__ bet,
                  float* __restrict__ out0, float* __restrict__ out1,
                  const float* __restrict__ qkv)
{
    extern __shared__ char smc[];
    const int tid  = threadIdx.x;
    const int w    = tid >> 5;
    const int lane = tid & 31;
    const int g    = lane >> 2;
    const int t4   = lane & 3;
    const int wm   = (w >> 2) * 64;
    const int wn   = (w & 3) * 64;
    const int m0   = blockIdx.y * 128;
    const uint32_t sb = smem_to_u32(smc);

    float* bias_s = (float*)(smc);
    float* gam_s  = (float*)(smc + 1024);
    float* bet_s  = (float*)(smc + 2048);
    float* qs     = (float*)(smc + 3072);

    bias_s[tid] = bias[tid];
    gam_s[tid] = gam[tid]; bet_s[tid] = bet[tid];
    const int bq = m0 >> 16;
    const int ib = (m0 >> 8) & 255;
    const int jb = m0 & 255;
    qs[tid] = qkv[(size_t)(bq * 256 + ib) * 768 + tid];
    __syncthreads();

    float acc[4][8][4];
#pragma unroll
    for (int mi = 0; mi < 4; mi++)
#pragma unroll
        for (int ni = 0; ni < 8; ni++)
#pragma unroll
            for (int c = 0; c < 4; c++) acc[mi][ni][c] = 0.f;

    auto issueW = [&](int ch, int s) {
        const int k0 = ch * 32;
        const uint32_t sW = sb + 4096 + s * 49152 + 16384;
#pragma unroll
        for (int i2 = 0; i2 < 8; i2++) {
            int c = tid + i2 * 256;
            int r = c >> 3, kc = (c & 7) * 4;
            cp16(sW + r * 128 + ((kc * 4) ^ ((r & 7) * 16)),
                 W + (size_t)r * 256 + k0 + kc);
        }
    };
    auto fuseA = [&](int ch, int s) {
        const int k0 = ch * 32;
        char* sA = smc + 4096 + s * 49152;
#pragma unroll
        for (int i2 = 0; i2 < 4; i2++) {
            int c = tid + i2 * 256;
            int r = c >> 3, kc = (c & 7) * 4;
            float4 e  = *(const float4*)(edges + (size_t)(m0 + r) * 256 + k0 + kc);
            float4 kv = *(const float4*)(qkv + (size_t)(bq * 256 + jb + r) * 768 + 256 + k0 + kc);
            float4 qv = *(const float4*)(qs + k0 + kc);
            float4 v;
            v.x = tf32r(qv.x * kv.x * 0.0625f + e.x);
            v.y = tf32r(qv.y * kv.y * 0.0625f + e.y);
            v.z = tf32r(qv.z * kv.z * 0.0625f + e.z);
            v.w = tf32r(qv.w * kv.w * 0.0625f + e.w);
            *(float4*)(sA + r * 128 + ((kc * 4) ^ ((r & 7) * 16))) = v;
        }
    };

    issueW(0, 0);
    cp_commit();
    for (int ch = 0; ch < 8; ch++) {
        const int s = ch & 1;
        fuseA(ch, s);
        if (ch + 1 < 8) { issueW(ch + 1, s ^ 1); cp_commit(); cp_wait<1>(); }
        else            { cp_wait<0>(); }
        __syncthreads();
        const char* As = smc + 4096 + s * 49152;
        const char* Ws = As + 16384;
#pragma unroll
        for (int ks = 0; ks < 4; ks++) {
            const int ka = ks * 8 + t4;
            const int kb = ka + 4;
            uint32_t afr[4][4];
#pragma unroll
            for (int mi = 0; mi < 4; mi++) {
                int r0 = wm + mi * 16 + g, r1 = r0 + 8;
                afr[mi][0] = *(const uint32_t*)(As + r0 * 128 + ((ka * 4) ^ ((r0 & 7) * 16)));
                afr[mi][1] = *(const uint32_t*)(As + r1 * 128 + ((ka * 4) ^ ((r1 & 7) * 16)));
                afr[mi][2] = *(const uint32_t*)(As + r0 * 128 + ((kb * 4) ^ ((r0 & 7) * 16)));
                afr[mi][3] = *(const uint32_t*)(As + r1 * 128 + ((kb * 4) ^ ((r1 & 7) * 16)));
            }
#pragma unroll
            for (int ni = 0; ni < 8; ni++) {
                int nr = wn + ni * 8 + g;
                uint32_t bfr[2];
                bfr[0] = *(const uint32_t*)(Ws + nr * 128 + ((ka * 4) ^ ((nr & 7) * 16)));
                bfr[1] = *(const uint32_t*)(Ws + nr * 128 + ((kb * 4) ^ ((nr & 7) * 16)));
#pragma unroll
                for (int mi = 0; mi < 4; mi++) mma_tf32(acc[mi][ni], afr[mi], bfr);
            }
        }
        __syncthreads();
    }

    // LN1 epilogue -> T (fp32) + Tr (tf32)
    float* rsum = (float*)(smc + 4096);
    float* rsq  = (float*)(smc + 4096 + 2048);
#pragma unroll
    for (int mi = 0; mi < 4; mi++)
#pragma unroll
        for (int h = 0; h < 2; h++) {
            int rl = wm + mi * 16 + g + h * 8;
            const float* rr = edges + (size_t)(m0 + rl) * 256;
            float s = 0.f, q = 0.f;
#pragma unroll
            for (int ni = 0; ni < 8; ni++) {
                int col = wn + ni * 8 + t4 * 2;
                float2 rv = *(const float2*)(rr + col);
                float v0 = fmaxf(acc[mi][ni][h * 2]     + bias_s[col], 0.f)     + rv.x;
                float v1 = fmaxf(acc[mi][ni][h * 2 + 1] + bias_s[col + 1], 0.f) + rv.y;
                s += v0 + v1;
                q += v0 * v0 + v1 * v1;
            }
            s += __shfl_xor_sync(0xFFFFFFFFu, s, 1);
            s += __shfl_xor_sync(0xFFFFFFFFu, s, 2);
            q += __shfl_xor_sync(0xFFFFFFFFu, q, 1);
            q += __shfl_xor_sync(0xFFFFFFFFu, q, 2);
            if (t4 == 0) {
                rsum[rl * 4 + (w & 3)] = s;
                rsq [rl * 4 + (w & 3)] = q;
            }
        }
    __syncthreads();
#pragma unroll
    for (int mi = 0; mi < 4; mi++)
#pragma unroll
        for (int h = 0; h < 2; h++) {
            int rl = wm + mi * 16 + g + h * 8;
            float tot = rsum[rl * 4] + rsum[rl * 4 + 1] + rsum[rl * 4 + 2] + rsum[rl * 4 + 3];
            float tq  = rsq [rl * 4] + rsq [rl * 4 + 1] + rsq [rl * 4 + 2] + rsq [rl * 4 + 3];
            float mean = tot * (1.f / 256.f);
            float var  = tq * (1.f / 256.f) - mean * mean;
            float inv  = rsqrtf(var + 1e-5f);
            const float* rr = edges + (size_t)(m0 + rl) * 256;
            size_t orow = (size_t)(m0 + rl) * 256;
#pragma unroll
            for (int ni = 0; ni < 8; ni++) {
                int col = wn + ni * 8 + t4 * 2;
                float2 rv = *(const float2*)(rr + col);
                float v0 = fmaxf(acc[mi][ni][h * 2]     + bias_s[col], 0.f)     + rv.x;
                float v1 = fmaxf(acc[mi][ni][h * 2 + 1] + bias_s[col + 1], 0.f) + rv.y;
                float o0 = (v0 - mean) * inv * gam_s[col]     + bet_s[col];
                float o1 = (v1 - mean) * inv * gam_s[col + 1] + bet_s[col + 1];
                *(float2*)(out0 + orow + col) = make_float2(o0, o1);
                *(float2*)(out1 + orow + col) = make_float2(tf32r(o0), tf32r(o1));
            }
        }
}

// ======================= fused edge MLP: out = LN2(relu(Tr@We1^T+be1)@We2^T + be2 + T) =======================
// Per CTA: 128 rows x 256 out cols. Hidden (1024) in 8 chunks of 128:
//   phase A: HMc[128x128] = tf32r(relu(Tr_blk @ We1_slice^T + be1)) -> SMEM (swizzled A layout)
//   phase B: outacc += HMc @ We2_slice^T (K=128, A straight from SMEM)
// smem: [0,1K) be2 | [1K,2K) gam | [2K,3K) bet | [3K,7K) LN red | [8K,72K) HMc |
//       [72K,104K) stage0 | [104K,136K) stage1
#define ML_HMC  8192
#define ML_ST0  73728
#define ML_ST1  106496
#define ML_SMEM 139264

__global__ __launch_bounds__(256)
void mlp_kernel(const float* __restrict__ Tr, const float* __restrict__ We1,
                const float* __restrict__ be1, const float* __restrict__ We2,
                const float* __restrict__ be2, const float* __restrict__ T,
                const float* __restrict__ gam, const float* __restrict__ bet,
                float* __restrict__ out)
{
    extern __shared__ char smc[];
    const uint32_t sb = smem_to_u32(smc);
    const int tid  = threadIdx.x;
    const int w    = tid >> 5;
    const int lane = tid & 31;
    const int g    = lane >> 2;
    const int t4   = lane & 3;
    const int wm   = (w >> 2) * 64;      // rows: 0 or 64
    const int wn   = (w & 3) * 64;       // phase-B cols: 0..192
    const int wnA  = (w & 3) * 32;       // phase-A cols: 0..96
    const int m0   = blockIdx.x * 128;

    float* bias_s = (float*)(smc);
    float* gam_s  = (float*)(smc + 1024);
    float* bet_s  = (float*)(smc + 2048);
    bias_s[tid] = be2[tid];
    gam_s[tid]  = gam[tid];
    bet_s[tid]  = bet[tid];

    float outacc[4][8][4];
#pragma unroll
    for (int mi = 0; mi < 4; mi++)
#pragma unroll
        for (int ni = 0; ni < 8; ni++)
#pragma unroll
            for (int c = 0; c < 4; c++) outacc[mi][ni][c] = 0.f;

    auto issueA = [&](int h, int ch, int s) {
        const int k0 = ch * 32;
        const uint32_t sA = sb + (s ? ML_ST1 : ML_ST0);
        const uint32_t sW = sA + 16384;
#pragma unroll
        for (int i2 = 0; i2 < 4; i2++) {
            int c = tid + i2 * 256;
            int r = c >> 3, kc = (c & 7) * 4;
            uint32_t sw = (uint32_t)((kc * 4) ^ ((r & 7) * 16));
            cp16(sA + r * 128 + sw, Tr  + (size_t)(m0 + r) * 256 + k0 + kc);
            cp16(sW + r * 128 + sw, We1 + (size_t)(h * 128 + r) * 256 + k0 + kc);
        }
        cp_commit();
    };
    auto issueB = [&](int h, int ch, int s) {
        const int k0 = ch * 32;
        const uint32_t sW = sb + (s ? ML_ST1 : ML_ST0);
#pragma unroll
        for (int i2 = 0; i2 < 8; i2++) {
            int c = tid + i2 * 256;
            int r = c >> 3, kc = (c & 7) * 4;
            cp16(sW + r * 128 + ((kc * 4) ^ ((r & 7) * 16)),
                 We2 + (size_t)r * 1024 + h * 128 + k0 + kc);
        }
        cp_commit();
    };

    issueA(0, 0, 0);

    for (int h = 0; h < 8; h++) {
        // -------- phase A --------
        float accA[4][4][4];
#pragma unroll
        for (int mi = 0; mi < 4; mi++)
#pragma unroll
            for (int ni = 0; ni < 4; ni++)
#pragma unroll
                for (int c = 0; c < 4; c++) accA[mi][ni][c] = 0.f;

        for (int ch = 0; ch < 8; ch++) {
            const int s = ch & 1;
            if (ch + 1 < 8) { issueA(h, ch + 1, s ^ 1); cp_wait<1>(); }
            else            { cp_wait<0>(); }
            __syncthreads();
            const char* As = smc + (s ? ML_ST1 : ML_ST0);
            const char* Ws = As + 16384;
#pragma unroll
            for (int ks = 0; ks < 4; ks++) {
                const int ka = ks * 8 + t4;
                const int kb = ka + 4;
                uint32_t afr[4][4];
#pragma unroll
                for (int mi = 0; mi < 4; mi++) {
                    int r0 = wm + mi * 16 + g, r1 = r0 + 8;
                    afr[mi][0] = *(const uint32_t*)(As + r0 * 128 + ((ka * 4) ^ ((r0 & 7) * 16)));
                    afr[mi][1] = *(const uint32_t*)(As + r1 * 128 + ((ka * 4) ^ ((r1 & 7) * 16)));
                    afr[mi][2] = *(const uint32_t*)(As + r0 * 128 + ((kb * 4) ^ ((r0 & 7) * 16)));
                    afr[mi][3] = *(const uint32_t*)(As + r1 * 128 + ((kb * 4) ^ ((r1 & 7) * 16)));
                }
#pragma unroll
                for (int ni = 0; ni < 4; ni++) {
                    int nr = wnA + ni * 8 + g;
                    uint32_t bfr[2];
                    bfr[0] = *(const uint32_t*)(Ws + nr * 128 + ((ka * 4) ^ ((nr & 7) * 16)));
                    bfr[1] = *(const uint32_t*)(Ws + nr * 128 + ((kb * 4) ^ ((nr & 7) * 16)));
#pragma unroll
                    for (int mi = 0; mi < 4; mi++) mma_tf32(accA[mi][ni], afr[mi], bfr);
                }
            }
            __syncthreads();
        }

        // prefetch phase-B chunk 0 while doing phase-A epilogue
        issueB(h, 0, 0);

        // epilogue A: bias+relu+tf32 round -> HMc smem (swizzled A layout, row stride 512B)
#pragma unroll
        for (int mi = 0; mi < 4; mi++)
#pragma unroll
            for (int hh = 0; hh < 2; hh++) {
                int r = wm + mi * 16 + g + hh * 8;
#pragma unroll
                for (int ni = 0; ni < 4; ni++) {
                    int k = wnA + ni * 8 + t4 * 2;
                    float b0 = be1[h * 128 + k];
                    float b1 = be1[h * 128 + k + 1];
                    float v0 = tf32r(fmaxf(accA[mi][ni][hh * 2]     + b0, 0.f));
                    float v1 = tf32r(fmaxf(accA[mi][ni][hh * 2 + 1] + b1, 0.f));
                    *(float2*)(smc + ML_HMC + r * 512 + ((k * 4) ^ ((r & 7) * 16))) =
                        make_float2(v0, v1);
                }
            }
        __syncthreads();

        // -------- phase B: outacc += HMc @ We2_slice^T --------
        for (int ch = 0; ch < 4; ch++) {
            const int s = ch & 1;
            if (ch + 1 < 4) { issueB(h, ch + 1, s ^ 1); cp_wait<1>(); }
            else {
                if (h + 1 < 8) { issueA(h + 1, 0, 0); cp_wait<1>(); }
                else           { cp_wait<0>(); }
            }
            __syncthreads();
            const char* As = smc + ML_HMC;
            const char* Ws = smc + (s ? ML_ST1 : ML_ST0);
#pragma unroll
            for (int ks = 0; ks < 4; ks++) {
                const int kl = ch * 32 + ks * 8 + t4;   // 0..127 within HMc
                const int klb = kl + 4;
                const int kw = ks * 8 + t4;             // 0..31 within staged W
                const int kwb = kw + 4;
                uint32_t afr[4][4];
#pragma unroll
                for (int mi = 0; mi < 4; mi++) {
                    int r0 = wm + mi * 16 + g, r1 = r0 + 8;
                    afr[mi][0] = *(const uint32_t*)(As + r0 * 512 + ((kl * 4)  ^ ((r0 & 7) * 16)));
                    afr[mi][1] = *(const uint32_t*)(As + r1 * 512 + ((kl * 4)  ^ ((r1 & 7) * 16)));
                    afr[mi][2] = *(const uint32_t*)(As + r0 * 512 + ((klb * 4) ^ ((r0 & 7) * 16)));
                    afr[mi][3] = *(const uint32_t*)(As + r1 * 512 + ((klb * 4) ^ ((r1 & 7) * 16)));
                }
#pragma unroll
                for (int ni = 0; ni < 8; ni++) {
                    int nr = wn + ni * 8 + g;
                    uint32_t bfr[2];
                    bfr[0] = *(const uint32_t*)(Ws + nr * 128 + ((kw * 4)  ^ ((nr & 7) * 16)));
                    bfr[1] = *(const uint32_t*)(Ws + nr * 128 + ((kwb * 4) ^ ((nr & 7) * 16)));
#pragma unroll
                    for (int mi = 0; mi < 4; mi++) mma_tf32(outacc[mi][ni], afr[mi], bfr);
                }
            }
            __syncthreads();
        }
    }

    // -------- final LN2 epilogue: v = outacc + be2 + T; LN -> out --------
    float* rsum = (float*)(smc + 3072);
    float* rsq  = (float*)(smc + 5120);
#pragma unroll
    for (int mi = 0; mi < 4; mi++)
#pragma unroll
        for (int hh = 0; hh < 2; hh++) {
            int rl = wm + mi * 16 + g + hh * 8;
            const float* rr = T + (size_t)(m0 + rl) * 256;
            float s = 0.f, q = 0.f;
#pragma unroll
            for (int ni = 0; ni < 8; ni++) {
                int col = wn + ni * 8 + t4 * 2;
                float2 rv = *(const float2*)(rr + col);
                float v0 = outacc[mi][ni][hh * 2]     + bias_s[col]     + rv.x;
                float v1 = outacc[mi][ni][hh * 2 + 1] + bias_s[col + 1] + rv.y;
                s += v0 + v1;
                q += v0 * v0 + v1 * v1;
            }
            s += __shfl_xor_sync(0xFFFFFFFFu, s, 1);
            s += __shfl_xor_sync(0xFFFFFFFFu, s, 2);
            q += __shfl_xor_sync(0xFFFFFFFFu, q, 1);
            q += __shfl_xor_sync(0xFFFFFFFFu, q, 2);
            if (t4 == 0) {
                rsum[rl * 4 + (w & 3)] = s;
                rsq [rl * 4 + (w & 3)] = q;
            }
        }
    __syncthreads();
#pragma unroll
    for (int mi = 0; mi < 4; mi++)
#pragma unroll
        for (int hh = 0; hh < 2; hh++) {
            int rl = wm + mi * 16 + g + hh * 8;
            float tot = rsum[rl * 4] + rsum[rl * 4 + 1] + rsum[rl * 4 + 2] + rsum[rl * 4 + 3];
            float tq  = rsq [rl * 4] + rsq [rl * 4 + 1] + rsq [rl * 4 + 2] + rsq [rl * 4 + 3];
            float mean = tot * (1.f / 256.f);
            float var  = tq * (1.f / 256.f) - mean * mean;
            float inv  = rsqrtf(var + 1e-5f);
            const float* rr = T + (size_t)(m0 + rl) * 256;
            size_t orow = (size_t)(m0 + rl) * 256;
#pragma unroll
            for (int ni = 0; ni < 8; ni++) {
                int col = wn + ni * 8 + t4 * 2;
                float2 rv = *(const float2*)(rr + col);
                float v0 = outacc[mi][ni][hh * 2]     + bias_s[col]     + rv.x;
                float v1 = outacc[mi][ni][hh * 2 + 1] + bias_s[col + 1] + rv.y;
                float o0 = (v0 - mean) * inv * gam_s[col]     + bet_s[col];
                float o1 = (v1 - mean) * inv * gam_s[col + 1] + bet_s[col + 1];
                *(float2*)(out + orow + col) = make_float2(o0, o1);
            }
        }
}

// ======================= launch =======================
extern "C" void kernel_launch(void* const* d_in, const int* in_sizes, int n_in,
                              void* d_out, int out_size)
{
    const float* nodes = (const float*)d_in[0];
    const float* edges = (const float*)d_in[1];
    const float* conds = (const float*)d_in[2];
    const float* Wqkv  = (const float*)d_in[3];
    const float* bqkv  = (const float*)d_in[4];
    const float* Wno   = (const float*)d_in[5];
    const float* bno   = (const float*)d_in[6];
    const float* Weo   = (const float*)d_in[7];
    const float* beo   = (const float*)d_in[8];
    const float* g1n   = (const float*)d_in[9];
    const float* b1n   = (const float*)d_in[10];
    const float* g1e   = (const float*)d_in[11];
    const float* b1e   = (const float*)d_in[12];
    const float* Wn1   = (const float*)d_in[13];
    const float* bn1   = (const float*)d_in[14];
    const float* Wn2   = (const float*)d_in[15];
    const float* bn2   = (const float*)d_in[16];
    const float* We1   = (const float*)d_in[17];
    const float* be1   = (const float*)d_in[18];
    const float* We2   = (const float*)d_in[19];
    const float* be2   = (const float*)d_in[20];
    const float* g2n   = (const float*)d_in[21];
    const float* b2n   = (const float*)d_in[22];
    const float* g2e   = (const float*)d_in[23];
    const float* b2e   = (const float*)d_in[24];

    float *X, *QKV, *WV, *N1, *NA, *NH, *NO;
    float *T, *Tr, *Weor, *We1r, *We2r;
    cudaGetSymbolAddress((void**)&X,    g_X);
    cudaGetSymbolAddress((void**)&QKV,  g_qkv);
    cudaGetSymbolAddress((void**)&WV,   g_wv);
    cudaGetSymbolAddress((void**)&N1,   g_n1);
    cudaGetSymbolAddress((void**)&NA,   g_nA);
    cudaGetSymbolAddress((void**)&NH,   g_nh);
    cudaGetSymbolAddress((void**)&NO,   g_no);
    cudaGetSymbolAddress((void**)&T,    g_T);
    cudaGetSymbolAddress((void**)&Tr,   g_Tr);
    cudaGetSymbolAddress((void**)&Weor, g_Weor);
    cudaGetSymbolAddress((void**)&We1r, g_We1r);
    cudaGetSymbolAddress((void**)&We2r, g_We2r);

    float* out_nodes = (float*)d_out;
    float* out_edges = out_nodes + SZ_NODES;
    float* out_conds = out_edges + SZ_EDGES;

    cudaFuncSetAttribute(gemm1_kernel, cudaFuncAttributeMaxDynamicSharedMemorySize, TC_SMEM);
    cudaFuncSetAttribute(mlp_kernel,   cudaFuncAttributeMaxDynamicSharedMemorySize, ML_SMEM);

    // weight rounding (tiny)
    wround_kernel<<<256,  256>>>(Weo, Weor, 256 * 256);
    wround_kernel<<<1024, 256>>>(We1, We1r, 1024 * 256);
    wround_kernel<<<1024, 256>>>(We2, We2r, 256 * 1024);

    // node/attention path (fp32, small)
    x_kernel<<<512, 256>>>(nodes, conds, X);
    sgemm_kernel<false><<<dim3(6, 4),   256>>>(X,  Wqkv, bqkv, QKV, 512, 768, 256);
    attn_kernel<<<dim3(256, 8, 2), 256>>>(QKV, edges, WV);
    sgemm_kernel<false><<<dim3(2, 4),   256>>>(WV, Wno,  bno,  N1,  512, 256, 256);
    ln_kernel<<<512, 256>>>(N1, nodes, g1n, b1n, NA);
    sgemm_kernel<true ><<<dim3(8, 4),   256>>>(NA, Wn1,  bn1,  NH,  512, 1024, 256);
    sgemm_kernel<false><<<dim3(2, 4),   256>>>(NH, Wn2,  bn2,  NO,  512, 256, 1024);
    ln_kernel<<<512, 256>>>(NO, NA, g2n, b2n, out_nodes);

    // edge path
    // GEMM1: build R in-loader, GEMM vs Weo, relu+bias, +edges, LN1 -> T, Tr
    gemm1_kernel<<<dim3(1, 1024), 256, TC_SMEM>>>(
        edges, Weor, beo, g1e, b1e, T, Tr, QKV);
    // fused MLP: out_edges = LN2(relu(Tr@We1^T+be1)@We2^T + be2 + T)
    mlp_kernel<<<1024, 256, ML_SMEM>>>(
        Tr, We1r, be1, We2r, be2, T, g2e, b2e, out_edges);

    copy_conds<<<1, 512>>>(conds, out_conds);
}

// round 10
// speedup vs baseline: 1.0184x; 1.0184x over previous
#include <cuda_runtime.h>
#include <cuda_bf16.h>
#include <math.h>
#include <stdint.h>

// Problem constants
#define Bb 2
#define Nn 256
#define Dd 256
#define Ee 256
#define SZ_NODES (Bb*Nn*Dd)            // 131072
#define SZ_EDGES ((size_t)Bb*Nn*Nn*Ee) // 33554432
#define M_EDGE   (Bb*Nn*Nn)            // 131072

// ======================= helpers =======================
__device__ __forceinline__ uint32_t smem_to_u32(const void* smem_ptr) {
    uint32_t addr;
    asm("{ .reg .u64 tmp; cvta.to.shared.u64 tmp, %1; cvt.u32.u64 %0, tmp; }"
        : "=r"(addr) : "l"(smem_ptr));
    return addr;
}
__device__ __forceinline__ float tf32r(float x) {
    uint32_t u;
    asm("cvt.rna.tf32.f32 %0, %1;" : "=r"(u) : "f"(x));
    return __uint_as_float(u);
}
__device__ __forceinline__ void cp16(uint32_t dst, const void* src) {
    asm volatile("cp.async.cg.shared.global [%0], [%1], 16;" :: "r"(dst), "l"(src));
}
__device__ __forceinline__ void cp_commit() {
    asm volatile("cp.async.commit_group;");
}
template<int NMAX>
__device__ __forceinline__ void cp_wait() {
    asm volatile("cp.async.wait_group %0;" :: "n"(NMAX));
}
__device__ __forceinline__ void mma_tf32(float* d, const uint32_t* a, const uint32_t* b) {
    asm volatile(
        "mma.sync.aligned.m16n8k8.row.col.f32.tf32.tf32.f32 "
        "{%0,%1,%2,%3},{%4,%5,%6,%7},{%8,%9},{%0,%1,%2,%3};"
        : "+f"(d[0]), "+f"(d[1]), "+f"(d[2]), "+f"(d[3])
        : "r"(a[0]), "r"(a[1]), "r"(a[2]), "r"(a[3]), "r"(b[0]), "r"(b[1]));
}

// ======================= scratch (static device memory) =======================
__device__ float g_X  [512*256];
__device__ float g_qkv[512*768];
__device__ float g_wv [512*256];
__device__ float g_n1 [512*256];
__device__ float g_nA [512*256];
__device__ float g_nh [512*1024];
__device__ float g_no [512*256];

__device__ float g_T  [(size_t)M_EDGE*256];   // exact LN1 output
__device__ float g_Tr [(size_t)M_EDGE*256];   // tf32-rounded copy
__device__ float g_Hm [(size_t)M_EDGE*1024];  // rounded MLP hidden
__device__ float g_Weor[256*256];
__device__ float g_We1r[1024*256];
__device__ float g_We2r[256*1024];

// ======================= small kernels =======================
__global__ void x_kernel(const float* __restrict__ nodes,
                         const float* __restrict__ conds,
                         float* __restrict__ X)
{
    int idx = blockIdx.x * 256 + threadIdx.x;
    int b = idx >> 16;
    int d = idx & 255;
    X[idx] = nodes[idx] + conds[b * 256 + d];
}

__global__ void wround_kernel(const float* __restrict__ s, float* __restrict__ d, int n)
{
    int i = blockIdx.x * 256 + threadIdx.x;
    if (i < n) d[i] = tf32r(s[i]);
}

// ---------------- fp32 SGEMM for the (small) node path ----------------
template<bool RELU>
__global__ __launch_bounds__(256, 2)
void sgemm_kernel(const float* __restrict__ A, const float* __restrict__ W,
                  const float* __restrict__ bias, float* __restrict__ C,
                  int M, int N, int K)
{
    __shared__ float As[16][128];
    __shared__ float Ws[16][128];
    const int tid  = threadIdx.x;
    const int tx   = tid & 15;
    const int ty   = tid >> 4;
    const int lrow = tid >> 2;
    const int lcol = (tid & 3) << 2;
    const float* Ab = A + (size_t)blockIdx.y * 128 * K;
    const float* Wb = W + (size_t)blockIdx.x * 128 * K;
    float acc[8][8];
#pragma unroll
    for (int r = 0; r < 8; r++)
#pragma unroll
        for (int c = 0; c < 8; c++) acc[r][c] = 0.f;
    for (int k0 = 0; k0 < K; k0 += 16) {
        float4 a0 = *(const float4*)(Ab + (size_t)lrow        * K + k0 + lcol);
        float4 a1 = *(const float4*)(Ab + (size_t)(lrow + 64) * K + k0 + lcol);
        float4 w0 = *(const float4*)(Wb + (size_t)lrow        * K + k0 + lcol);
        float4 w1 = *(const float4*)(Wb + (size_t)(lrow + 64) * K + k0 + lcol);
        __syncthreads();
        As[lcol+0][lrow]    = a0.x; As[lcol+1][lrow]    = a0.y;
        As[lcol+2][lrow]    = a0.z; As[lcol+3][lrow]    = a0.w;
        As[lcol+0][lrow+64] = a1.x; As[lcol+1][lrow+64] = a1.y;
        As[lcol+2][lrow+64] = a1.z; As[lcol+3][lrow+64] = a1.w;
        Ws[lcol+0][lrow]    = w0.x; Ws[lcol+1][lrow]    = w0.y;
        Ws[lcol+2][lrow]    = w0.z; Ws[lcol+3][lrow]    = w0.w;
        Ws[lcol+0][lrow+64] = w1.x; Ws[lcol+1][lrow+64] = w1.y;
        Ws[lcol+2][lrow+64] = w1.z; Ws[lcol+3][lrow+64] = w1.w;
        __syncthreads();
#pragma unroll
        for (int kk = 0; kk < 16; kk++) {
            float a[8], wv[8];
            *(float4*)(a)      = *(const float4*)&As[kk][ty * 4];
            *(float4*)(a + 4)  = *(const float4*)&As[kk][64 + ty * 4];
            *(float4*)(wv)     = *(const float4*)&Ws[kk][tx * 4];
            *(float4*)(wv + 4) = *(const float4*)&Ws[kk][64 + tx * 4];
#pragma unroll
            for (int r = 0; r < 8; r++)
#pragma unroll
                for (int c = 0; c < 8; c++) acc[r][c] += a[r] * wv[c];
        }
    }
    float bv[8];
#pragma unroll
    for (int c = 0; c < 8; c++) {
        int n = blockIdx.x * 128 + ((c < 4) ? (tx * 4 + c) : (64 + tx * 4 + (c - 4)));
        bv[c] = bias[n];
    }
#pragma unroll
    for (int r = 0; r < 8; r++) {
        int row = blockIdx.y * 128 + ((r < 4) ? (ty * 4 + r) : (64 + ty * 4 + (r - 4)));
        float4 o0, o1; float v;
        v = acc[r][0] + bv[0]; if (RELU) v = fmaxf(v, 0.f); o0.x = v;
        v = acc[r][1] + bv[1]; if (RELU) v = fmaxf(v, 0.f); o0.y = v;
        v = acc[r][2] + bv[2]; if (RELU) v = fmaxf(v, 0.f); o0.z = v;
        v = acc[r][3] + bv[3]; if (RELU) v = fmaxf(v, 0.f); o0.w = v;
        v = acc[r][4] + bv[4]; if (RELU) v = fmaxf(v, 0.f); o1.x = v;
        v = acc[r][5] + bv[5]; if (RELU) v = fmaxf(v, 0.f); o1.y = v;
        v = acc[r][6] + bv[6]; if (RELU) v = fmaxf(v, 0.f); o1.z = v;
        v = acc[r][7] + bv[7]; if (RELU) v = fmaxf(v, 0.f); o1.w = v;
        float* Crow = C + (size_t)row * N + blockIdx.x * 128;
        *(float4*)(Crow + tx * 4)      = o0;
        *(float4*)(Crow + 64 + tx * 4) = o1;
    }
}

// ---------------- attention ----------------
__global__ __launch_bounds__(256)
void attn_kernel(const float* __restrict__ qkv, const float* __restrict__ edges,
                 float* __restrict__ wv)
{
    int i = blockIdx.x, h = blockIdx.y, b = blockIdx.z;
    __shared__ __align__(16) float q[32];
    __shared__ float p[256];
    __shared__ float red[256];
    __shared__ float pv[8][32];
    int tid = threadIdx.x;
    if (tid < 32) q[tid] = qkv[((size_t)(b * 256 + i)) * 768 + h * 32 + tid];
    __syncthreads();
    int j = tid;
    const float4* k4 = (const float4*)(qkv + ((size_t)(b * 256 + j)) * 768 + 256 + h * 32);
    const float4* e4 = (const float4*)(edges + (((size_t)(b * 256 + i)) * 256 + j) * 256 + h * 32);
    float dot = 0.f, es = 0.f;
#pragma unroll
    for (int d4 = 0; d4 < 8; d4++) {
        float4 kv = k4[d4]; float4 ev = e4[d4];
        float4 qv = *(const float4*)&q[d4 * 4];
        dot += qv.x * kv.x + qv.y * kv.y + qv.z * kv.z + qv.w * kv.w;
        es  += ev.x + ev.y + ev.z + ev.w;
    }
    float logit = dot * 0.0625f + es;
    red[tid] = logit; __syncthreads();
    for (int s = 128; s > 0; s >>= 1) {
        if (tid < s) red[tid] = fmaxf(red[tid], red[tid + s]);
        __syncthreads();
    }
    float mx = red[0];
    __syncthreads();
    float e = expf(logit - mx);
    p[tid] = e; red[tid] = e; __syncthreads();
    for (int s = 128; s > 0; s >>= 1) {
        if (tid < s) red[tid] += red[tid + s];
        __syncthreads();
    }
    float inv = 1.f / red[0];
    int d = tid & 31, g = tid >> 5;
    float acc = 0.f;
    for (int jj = g * 32; jj < g * 32 + 32; jj++)
        acc += p[jj] * qkv[((size_t)(b * 256 + jj)) * 768 + 512 + h * 32 + d];
    pv[g][d] = acc;
    __syncthreads();
    if (tid < 32) {
        float s = 0.f;
#pragma unroll
        for (int g2 = 0; g2 < 8; g2++) s += pv[g2][tid];
        wv[((size_t)(b * 256 + i)) * 256 + h * 32 + tid] = s * inv;
    }
}

// ---------------- LayerNorm (node path only) ----------------
__global__ __launch_bounds__(256)
void ln_kernel(const float* __restrict__ x, const float* __restrict__ resid,
               const float* __restrict__ g, const float* __restrict__ bb,
               float* __restrict__ out)
{
    __shared__ float s1[256];
    __shared__ float s2[256];
    size_t row = blockIdx.x;
    int t = threadIdx.x;
    float v = x[row * 256 + t] + resid[row * 256 + t];
    s1[t] = v; s2[t] = v * v;
    __syncthreads();
    for (int s = 128; s > 0; s >>= 1) {
        if (t < s) { s1[t] += s1[t + s]; s2[t] += s2[t + s]; }
        __syncthreads();
    }
    float mean = s1[0] * (1.f / 256.f);
    float var  = s2[0] * (1.f / 256.f) - mean * mean;
    float inv  = rsqrtf(var + 1e-5f);
    out[row * 256 + t] = (v - mean) * inv * g[t] + bb[t];
}

__global__ void copy_conds(const float* __restrict__ c, float* __restrict__ o)
{
    o[threadIdx.x] = c[threadIdx.x];
}

// ======================= fused TF32 GEMM, CTA tile 128x256, warp tile 64x64 =======================
// 3-stage cp.async pipeline (loads issued two k-chunks ahead).
// EPI 0: out0 = tf32r(relu(acc+bias)), row length NFULL, col offset n0       (GEMM2 -> HM)
// EPI 1: v = relu(acc+bias)+resid; LN -> out0 (fp32 T) + out1 (tf32 Tr)      (GEMM1)
// EPI 2: v = acc+bias+resid;       LN -> out0 (fp32 out_edges)               (GEMM3)
// FUSEA: A computed on the fly: A[m,k] = tf32r(q_i[k]*k_j[k]/16 + edges[m,k])
// smem: [0,1K) bias | [1K,2K) gamma | [2K,3K) beta | [3K,4K) q | 3 stages @4K (48KB each)
#define TC_SMEM (4096 + 3*49152)

template<int EPI, bool RELU, bool FUSEA, int KT>
__global__ __launch_bounds__(256)
void tc2_gemm(const float* __restrict__ A, const float* __restrict__ W,
              const float* __restrict__ bias, const float* __restrict__ resid,
              const float* __restrict__ gam, const float* __restrict__ bet,
              float* __restrict__ out0, float* __restrict__ out1,
              int NFULL, const float* __restrict__ qkv)
{
    extern __shared__ char smc[];
    const uint32_t sb = smem_to_u32(smc);
    const int tid  = threadIdx.x;
    const int w    = tid >> 5;
    const int lane = tid & 31;
    const int g    = lane >> 2;
    const int t4   = lane & 3;
    const int wm   = (w >> 2) * 64;      // 0 or 64
    const int wn   = (w & 3) * 64;       // 0,64,128,192
    const int m0   = blockIdx.y * 128;
    const int n0   = blockIdx.x * 256;

    float* bias_s = (float*)(smc);
    float* gam_s  = (float*)(smc + 1024);
    float* bet_s  = (float*)(smc + 2048);
    float* qs     = (float*)(smc + 3072);

    bias_s[tid] = bias[n0 + tid];
    if (EPI != 0) { gam_s[tid] = gam[tid]; bet_s[tid] = bet[tid]; }
    int bq = 0, jb = 0;
    if (FUSEA) {
        bq = m0 >> 16;
        int ib = (m0 >> 8) & 255;
        jb = m0 & 255;
        qs[tid] = qkv[(size_t)(bq * 256 + ib) * 768 + tid];
    }
    __syncthreads();

    float acc[4][8][4];
#pragma unroll
    for (int mi = 0; mi < 4; mi++)
#pragma unroll
        for (int ni = 0; ni < 8; ni++)
#pragma unroll
            for (int c = 0; c < 4; c++) acc[mi][ni][c] = 0.f;

    auto issueW = [&](int ch, int s) {
        const int k0 = ch * 32;
        const uint32_t sW = sb + 4096 + s * 49152 + 16384;
#pragma unroll
        for (int i2 = 0; i2 < 8; i2++) {
            int c = tid + i2 * 256;
            int r = c >> 3, kc = (c & 7) * 4;
            cp16(sW + r * 128 + ((kc * 4) ^ ((r & 7) * 16)),
                 W + (size_t)(n0 + r) * KT + k0 + kc);
        }
    };
    auto issueA = [&](int ch, int s) {
        const int k0 = ch * 32;
        const uint32_t sA = sb + 4096 + s * 49152;
#pragma unroll
        for (int i2 = 0; i2 < 4; i2++) {
            int c = tid + i2 * 256;
            int r = c >> 3, kc = (c & 7) * 4;
            cp16(sA + r * 128 + ((kc * 4) ^ ((r & 7) * 16)),
                 A + (size_t)(m0 + r) * KT + k0 + kc);
        }
    };
    auto fuseA = [&](int ch, int s) {
        const int k0 = ch * 32;
        char* sA = smc + 4096 + s * 49152;
#pragma unroll
        for (int i2 = 0; i2 < 4; i2++) {
            int c = tid + i2 * 256;
            int r = c >> 3, kc = (c & 7) * 4;
            float4 e  = *(const float4*)(A + (size_t)(m0 + r) * 256 + k0 + kc);
            float4 kv = *(const float4*)(qkv + (size_t)(bq * 256 + jb + r) * 768 + 256 + k0 + kc);
            float4 qv = *(const float4*)(qs + k0 + kc);
            float4 v;
            v.x = tf32r(qv.x * kv.x * 0.0625f + e.x);
            v.y = tf32r(qv.y * kv.y * 0.0625f + e.y);
            v.z = tf32r(qv.z * kv.z * 0.0625f + e.z);
            v.w = tf32r(qv.w * kv.w * 0.0625f + e.w);
            *(float4*)(sA + r * 128 + ((kc * 4) ^ ((r & 7) * 16))) = v;
        }
    };

    const int NCH = KT / 32;
    // prime two stages ahead
    if (!FUSEA) issueA(0, 0);
    issueW(0, 0);
    cp_commit();
    if (NCH > 1) {
        if (!FUSEA) issueA(1, 1);
        issueW(1, 1);
        cp_commit();
    }

    for (int ch = 0; ch < NCH; ch++) {
        const int s = ch % 3;
        if (FUSEA) fuseA(ch, s);
        if (ch + 2 < NCH) {
            if (!FUSEA) issueA(ch + 2, (ch + 2) % 3);
            issueW(ch + 2, (ch + 2) % 3);
            cp_commit();
            cp_wait<2>();
        } else if (ch + 1 < NCH) {
            cp_wait<1>();
        } else {
            cp_wait<0>();
        }
        __syncthreads();

        const char* As = smc + 4096 + s * 49152;
        const char* Ws = As + 16384;
#pragma unroll
        for (int ks = 0; ks < 4; ks++) {
            const int ka = ks * 8 + t4;
            const int kb = ka + 4;
            uint32_t afr[4][4];
#pragma unroll
            for (int mi = 0; mi < 4; mi++) {
                int r0 = wm + mi * 16 + g, r1 = r0 + 8;
                afr[mi][0] = *(const uint32_t*)(As + r0 * 128 + ((ka * 4) ^ ((r0 & 7) * 16)));
                afr[mi][1] = *(const uint32_t*)(As + r1 * 128 + ((ka * 4) ^ ((r1 & 7) * 16)));
                afr[mi][2] = *(const uint32_t*)(As + r0 * 128 + ((kb * 4) ^ ((r0 & 7) * 16)));
                afr[mi][3] = *(const uint32_t*)(As + r1 * 128 + ((kb * 4) ^ ((r1 & 7) * 16)));
            }
#pragma unroll
            for (int ni = 0; ni < 8; ni++) {
                int nr = wn + ni * 8 + g;
                uint32_t bfr[2];
                bfr[0] = *(const uint32_t*)(Ws + nr * 128 + ((ka * 4) ^ ((nr & 7) * 16)));
                bfr[1] = *(const uint32_t*)(Ws + nr * 128 + ((kb * 4) ^ ((nr & 7) * 16)));
#pragma unroll
                for (int mi = 0; mi < 4; mi++) mma_tf32(acc[mi][ni], afr[mi], bfr);
            }
        }
        __syncthreads();
    }

    // ---------------- epilogue ----------------
    if (EPI == 0) {
#pragma unroll
        for (int mi = 0; mi < 4; mi++)
#pragma unroll
            for (int h = 0; h < 2; h++) {
                int r = m0 + wm + mi * 16 + g + h * 8;
                float* orow = out0 + (size_t)r * NFULL + n0;
#pragma unroll
                for (int ni = 0; ni < 8; ni++) {
                    int col = wn + ni * 8 + t4 * 2;
                    float v0 = acc[mi][ni][h * 2]     + bias_s[col];
                    float v1 = acc[mi][ni][h * 2 + 1] + bias_s[col + 1];
                    if (RELU) { v0 = fmaxf(v0, 0.f); v1 = fmaxf(v1, 0.f); }
                    *(float2*)(orow + col) = make_float2(tf32r(v0), tf32r(v1));
                }
            }
    } else {
        float* rsum = (float*)(smc + 4096);
        float* rsq  = (float*)(smc + 4096 + 2048);
#pragma unroll
        for (int mi = 0; mi < 4; mi++)
#pragma unroll
            for (int h = 0; h < 2; h++) {
                int rl = wm + mi * 16 + g + h * 8;
                const float* rr = resid + (size_t)(m0 + rl) * 256;
                float s = 0.f, q = 0.f;
#pragma unroll
                for (int ni = 0; ni < 8; ni++) {
                    int col = wn + ni * 8 + t4 * 2;
                    float2 rv = *(const float2*)(rr + col);
                    float v0 = acc[mi][ni][h * 2]     + bias_s[col];
                    float v1 = acc[mi][ni][h * 2 + 1] + bias_s[col + 1];
                    if (RELU) { v0 = fmaxf(v0, 0.f); v1 = fmaxf(v1, 0.f); }
                    v0 += rv.x; v1 += rv.y;
                    s += v0 + v1;
                    q += v0 * v0 + v1 * v1;
                }
                s += __shfl_xor_sync(0xFFFFFFFFu, s, 1);
                s += __shfl_xor_sync(0xFFFFFFFFu, s, 2);
                q += __shfl_xor_sync(0xFFFFFFFFu, q, 1);
                q += __shfl_xor_sync(0xFFFFFFFFu, q, 2);
                if (t4 == 0) {
                    rsum[rl * 4 + (w & 3)] = s;
                    rsq [rl * 4 + (w & 3)] = q;
                }
            }
        __syncthreads();
#pragma unroll
        for (int mi = 0; mi < 4; mi++)
#pragma unroll
            for (int h = 0; h < 2; h++) {
                int rl = wm + mi * 16 + g + h * 8;
                float tot = rsum[rl * 4] + rsum[rl * 4 + 1] + rsum[rl * 4 + 2] + rsum[rl * 4 + 3];
                float tq  = rsq [rl * 4] + rsq [rl * 4 + 1] + rsq [rl * 4 + 2] + rsq [rl * 4 + 3];
                float mean = tot * (1.f / 256.f);
                float var  = tq * (1.f / 256.f) - mean * mean;
                float inv  = rsqrtf(var + 1e-5f);
                const float* rr = resid + (size_t)(m0 + rl) * 256;
                size_t orow = (size_t)(m0 + rl) * 256;
#pragma unroll
                for (int ni = 0; ni < 8; ni++) {
                    int col = wn + ni * 8 + t4 * 2;
                    float2 rv = *(const float2*)(rr + col);
                    float v0 = acc[mi][ni][h * 2]     + bias_s[col];
                    float v1 = acc[mi][ni][h * 2 + 1] + bias_s[col + 1];
                    if (RELU) { v0 = fmaxf(v0, 0.f); v1 = fmaxf(v1, 0.f); }
                    v0 += rv.x; v1 += rv.y;
                    float o0 = (v0 - mean) * inv * gam_s[col]     + bet_s[col];
                    float o1 = (v1 - mean) * inv * gam_s[col + 1] + bet_s[col + 1];
                    *(float2*)(out0 + orow + col) = make_float2(o0, o1);
                    if (EPI == 1)
                        *(float2*)(out1 + orow + col) = make_float2(tf32r(o0), tf32r(o1));
                }
            }
    }
}

// ======================= launch =======================
extern "C" void kernel_launch(void* const* d_in, const int* in_sizes, int n_in,
                              void* d_out, int out_size)
{
    const float* nodes = (const float*)d_in[0];
    const float* edges = (const float*)d_in[1];
    const float* conds = (const float*)d_in[2];
    const float* Wqkv  = (const float*)d_in[3];
    const float* bqkv  = (const float*)d_in[4];
    const float* Wno   = (const float*)d_in[5];
    const float* bno   = (const float*)d_in[6];
    const float* Weo   = (const float*)d_in[7];
    const float* beo   = (const float*)d_in[8];
    const float* g1n   = (const float*)d_in[9];
    const float* b1n   = (const float*)d_in[10];
    const float* g1e   = (const float*)d_in[11];
    const float* b1e   = (const float*)d_in[12];
    const float* Wn1   = (const float*)d_in[13];
    const float* bn1   = (const float*)d_in[14];
    const float* Wn2   = (const float*)d_in[15];
    const float* bn2   = (const float*)d_in[16];
    const float* We1   = (const float*)d_in[17];
    const float* be1   = (const float*)d_in[18];
    const float* We2   = (const float*)d_in[19];
    const float* be2   = (const float*)d_in[20];
    const float* g2n   = (const float*)d_in[21];
    const float* b2n   = (const float*)d_in[22];
    const float* g2e   = (const float*)d_in[23];
    const float* b2e   = (const float*)d_in[24];

    float *X, *QKV, *WV, *N1, *NA, *NH, *NO;
    float *T, *Tr, *HM, *Weor, *We1r, *We2r;
    cudaGetSymbolAddress((void**)&X,    g_X);
    cudaGetSymbolAddress((void**)&QKV,  g_qkv);
    cudaGetSymbolAddress((void**)&WV,   g_wv);
    cudaGetSymbolAddress((void**)&N1,   g_n1);
    cudaGetSymbolAddress((void**)&NA,   g_nA);
    cudaGetSymbolAddress((void**)&NH,   g_nh);
    cudaGetSymbolAddress((void**)&NO,   g_no);
    cudaGetSymbolAddress((void**)&T,    g_T);
    cudaGetSymbolAddress((void**)&Tr,   g_Tr);
    cudaGetSymbolAddress((void**)&HM,   g_Hm);
    cudaGetSymbolAddress((void**)&Weor, g_Weor);
    cudaGetSymbolAddress((void**)&We1r, g_We1r);
    cudaGetSymbolAddress((void**)&We2r, g_We2r);

    float* out_nodes = (float*)d_out;
    float* out_edges = out_nodes + SZ_NODES;
    float* out_conds = out_edges + SZ_EDGES;

    cudaFuncSetAttribute(tc2_gemm<1, true,  true,  256>,
                         cudaFuncAttributeMaxDynamicSharedMemorySize, TC_SMEM);
    cudaFuncSetAttribute(tc2_gemm<0, true,  false, 256>,
                         cudaFuncAttributeMaxDynamicSharedMemorySize, TC_SMEM);
    cudaFuncSetAttribute(tc2_gemm<2, false, false, 1024>,
                         cudaFuncAttributeMaxDynamicSharedMemorySize, TC_SMEM);

    // weight rounding (tiny)
    wround_kernel<<<256,  256>>>(Weo, Weor, 256 * 256);
    wround_kernel<<<1024, 256>>>(We1, We1r, 1024 * 256);
    wround_kernel<<<1024, 256>>>(We2, We2r, 256 * 1024);

    // node/attention path (fp32, small)
    x_kernel<<<512, 256>>>(nodes, conds, X);
    sgemm_kernel<false><<<dim3(6, 4),   256>>>(X,  Wqkv, bqkv, QKV, 512, 768, 256);
    attn_kernel<<<dim3(256, 8, 2), 256>>>(QKV, edges, WV);
    sgemm_kernel<false><<<dim3(2, 4),   256>>>(WV, Wno,  bno,  N1,  512, 256, 256);
    ln_kernel<<<512, 256>>>(N1, nodes, g1n, b1n, NA);
    sgemm_kernel<true ><<<dim3(8, 4),   256>>>(NA, Wn1,  bn1,  NH,  512, 1024, 256);
    sgemm_kernel<false><<<dim3(2, 4),   256>>>(NH, Wn2,  bn2,  NO,  512, 256, 1024);
    ln_kernel<<<512, 256>>>(NO, NA, g2n, b2n, out_nodes);

    // edge path (fused tf32 tensor-core GEMMs, 3-stage pipeline)
    // GEMM1: build R in-loader, GEMM vs Weo, relu+bias, +edges, LN1 -> T, Tr
    tc2_gemm<1, true, true, 256><<<dim3(1, 1024), 256, TC_SMEM>>>(
        edges, Weor, beo, edges, g1e, b1e, T, Tr, 256, QKV);
    // GEMM2: HM = tf32r(relu(Tr @ We1^T + be1))
    tc2_gemm<0, true, false, 256><<<dim3(4, 1024), 256, TC_SMEM>>>(
        Tr, We1r, be1, nullptr, nullptr, nullptr, HM, nullptr, 1024, nullptr);
    // GEMM3: out_edges = LN(HM @ We2^T + be2 + T)
    tc2_gemm<2, false, false, 1024><<<dim3(1, 1024), 256, TC_SMEM>>>(
        HM, We2r, be2, T, g2e, b2e, out_edges, nullptr, 256, nullptr);

    copy_conds<<<1, 512>>>(conds, out_conds);
}

// round 12
// speedup vs baseline: 1.0889x; 1.0692x over previous
#include <cuda_runtime.h>
#include <cuda_bf16.h>
#include <math.h>
#include <stdint.h>

// Problem constants
#define Bb 2
#define Nn 256
#define Dd 256
#define Ee 256
#define SZ_NODES (Bb*Nn*Dd)            // 131072
#define SZ_EDGES ((size_t)Bb*Nn*Nn*Ee) // 33554432
#define M_EDGE   (Bb*Nn*Nn)            // 131072

// ======================= helpers =======================
__device__ __forceinline__ uint32_t smem_to_u32(const void* smem_ptr) {
    uint32_t addr;
    asm("{ .reg .u64 tmp; cvta.to.shared.u64 tmp, %1; cvt.u32.u64 %0, tmp; }"
        : "=r"(addr) : "l"(smem_ptr));
    return addr;
}
__device__ __forceinline__ float tf32r(float x) {
    uint32_t u;
    asm("cvt.rna.tf32.f32 %0, %1;" : "=r"(u) : "f"(x));
    return __uint_as_float(u);
}
__device__ __forceinline__ void cp16(uint32_t dst, const void* src) {
    asm volatile("cp.async.cg.shared.global [%0], [%1], 16;" :: "r"(dst), "l"(src));
}
__device__ __forceinline__ void cp_commit() {
    asm volatile("cp.async.commit_group;");
}
template<int NMAX>
__device__ __forceinline__ void cp_wait() {
    asm volatile("cp.async.wait_group %0;" :: "n"(NMAX));
}
__device__ __forceinline__ void mma_tf32(float* d, const uint32_t* a, const uint32_t* b) {
    asm volatile(
        "mma.sync.aligned.m16n8k8.row.col.f32.tf32.tf32.f32 "
        "{%0,%1,%2,%3},{%4,%5,%6,%7},{%8,%9},{%0,%1,%2,%3};"
        : "+f"(d[0]), "+f"(d[1]), "+f"(d[2]), "+f"(d[3])
        : "r"(a[0]), "r"(a[1]), "r"(a[2]), "r"(a[3]), "r"(b[0]), "r"(b[1]));
}

// ======================= scratch (static device memory) =======================
__device__ float g_X  [512*256];
__device__ float g_qkv[512*768];
__device__ float g_wv [512*256];
__device__ float g_n1 [512*256];
__device__ float g_nA [512*256];
__device__ float g_nh [512*1024];
__device__ float g_no [512*256];

__device__ float g_Tr [(size_t)M_EDGE*256];   // tf32-rounded LN1 output
__device__ float g_Hm [(size_t)M_EDGE*1024];  // rounded MLP hidden
__device__ float g_Weor[256*256];
__device__ float g_We1r[1024*256];
__device__ float g_We2r[256*1024];

// ======================= small kernels =======================
__global__ void x_kernel(const float* __restrict__ nodes,
                         const float* __restrict__ conds,
                         float* __restrict__ X)
{
    int idx = blockIdx.x * 256 + threadIdx.x;
    int b = idx >> 16;
    int d = idx & 255;
    X[idx] = nodes[idx] + conds[b * 256 + d];
}

__global__ void wround_kernel(const float* __restrict__ s, float* __restrict__ d, int n)
{
    int i = blockIdx.x * 256 + threadIdx.x;
    if (i < n) d[i] = tf32r(s[i]);
}

// ---------------- fp32 SGEMM for the (small) node path ----------------
template<bool RELU>
__global__ __launch_bounds__(256, 2)
void sgemm_kernel(const float* __restrict__ A, const float* __restrict__ W,
                  const float* __restrict__ bias, float* __restrict__ C,
                  int M, int N, int K)
{
    __shared__ float As[16][128];
    __shared__ float Ws[16][128];
    const int tid  = threadIdx.x;
    const int tx   = tid & 15;
    const int ty   = tid >> 4;
    const int lrow = tid >> 2;
    const int lcol = (tid & 3) << 2;
    const float* Ab = A + (size_t)blockIdx.y * 128 * K;
    const float* Wb = W + (size_t)blockIdx.x * 128 * K;
    float acc[8][8];
#pragma unroll
    for (int r = 0; r < 8; r++)
#pragma unroll
        for (int c = 0; c < 8; c++) acc[r][c] = 0.f;
    for (int k0 = 0; k0 < K; k0 += 16) {
        float4 a0 = *(const float4*)(Ab + (size_t)lrow        * K + k0 + lcol);
        float4 a1 = *(const float4*)(Ab + (size_t)(lrow + 64) * K + k0 + lcol);
        float4 w0 = *(const float4*)(Wb + (size_t)lrow        * K + k0 + lcol);
        float4 w1 = *(const float4*)(Wb + (size_t)(lrow + 64) * K + k0 + lcol);
        __syncthreads();
        As[lcol+0][lrow]    = a0.x; As[lcol+1][lrow]    = a0.y;
        As[lcol+2][lrow]    = a0.z; As[lcol+3][lrow]    = a0.w;
        As[lcol+0][lrow+64] = a1.x; As[lcol+1][lrow+64] = a1.y;
        As[lcol+2][lrow+64] = a1.z; As[lcol+3][lrow+64] = a1.w;
        Ws[lcol+0][lrow]    = w0.x; Ws[lcol+1][lrow]    = w0.y;
        Ws[lcol+2][lrow]    = w0.z; Ws[lcol+3][lrow]    = w0.w;
        Ws[lcol+0][lrow+64] = w1.x; Ws[lcol+1][lrow+64] = w1.y;
        Ws[lcol+2][lrow+64] = w1.z; Ws[lcol+3][lrow+64] = w1.w;
        __syncthreads();
#pragma unroll
        for (int kk = 0; kk < 16; kk++) {
            float a[8], wv[8];
            *(float4*)(a)      = *(const float4*)&As[kk][ty * 4];
            *(float4*)(a + 4)  = *(const float4*)&As[kk][64 + ty * 4];
            *(float4*)(wv)     = *(const float4*)&Ws[kk][tx * 4];
            *(float4*)(wv + 4) = *(const float4*)&Ws[kk][64 + tx * 4];
#pragma unroll
            for (int r = 0; r < 8; r++)
#pragma unroll
                for (int c = 0; c < 8; c++) acc[r][c] += a[r] * wv[c];
        }
    }
    float bv[8];
#pragma unroll
    for (int c = 0; c < 8; c++) {
        int n = blockIdx.x * 128 + ((c < 4) ? (tx * 4 + c) : (64 + tx * 4 + (c - 4)));
        bv[c] = bias[n];
    }
#pragma unroll
    for (int r = 0; r < 8; r++) {
        int row = blockIdx.y * 128 + ((r < 4) ? (ty * 4 + r) : (64 + ty * 4 + (r - 4)));
        float4 o0, o1; float v;
        v = acc[r][0] + bv[0]; if (RELU) v = fmaxf(v, 0.f); o0.x = v;
        v = acc[r][1] + bv[1]; if (RELU) v = fmaxf(v, 0.f); o0.y = v;
        v = acc[r][2] + bv[2]; if (RELU) v = fmaxf(v, 0.f); o0.z = v;
        v = acc[r][3] + bv[3]; if (RELU) v = fmaxf(v, 0.f); o0.w = v;
        v = acc[r][4] + bv[4]; if (RELU) v = fmaxf(v, 0.f); o1.x = v;
        v = acc[r][5] + bv[5]; if (RELU) v = fmaxf(v, 0.f); o1.y = v;
        v = acc[r][6] + bv[6]; if (RELU) v = fmaxf(v, 0.f); o1.z = v;
        v = acc[r][7] + bv[7]; if (RELU) v = fmaxf(v, 0.f); o1.w = v;
        float* Crow = C + (size_t)row * N + blockIdx.x * 128;
        *(float4*)(Crow + tx * 4)      = o0;
        *(float4*)(Crow + 64 + tx * 4) = o1;
    }
}

// ---------------- attention ----------------
__global__ __launch_bounds__(256)
void attn_kernel(const float* __restrict__ qkv, const float* __restrict__ edges,
                 float* __restrict__ wv)
{
    int i = blockIdx.x, h = blockIdx.y, b = blockIdx.z;
    __shared__ __align__(16) float q[32];
    __shared__ float p[256];
    __shared__ float red[256];
    __shared__ float pv[8][32];
    int tid = threadIdx.x;
    if (tid < 32) q[tid] = qkv[((size_t)(b * 256 + i)) * 768 + h * 32 + tid];
    __syncthreads();
    int j = tid;
    const float4* k4 = (const float4*)(qkv + ((size_t)(b * 256 + j)) * 768 + 256 + h * 32);
    const float4* e4 = (const float4*)(edges + (((size_t)(b * 256 + i)) * 256 + j) * 256 + h * 32);
    float dot = 0.f, es = 0.f;
#pragma unroll
    for (int d4 = 0; d4 < 8; d4++) {
        float4 kv = k4[d4]; float4 ev = e4[d4];
        float4 qv = *(const float4*)&q[d4 * 4];
        dot += qv.x * kv.x + qv.y * kv.y + qv.z * kv.z + qv.w * kv.w;
        es  += ev.x + ev.y + ev.z + ev.w;
    }
    float logit = dot * 0.0625f + es;
    red[tid] = logit; __syncthreads();
    for (int s = 128; s > 0; s >>= 1) {
        if (tid < s) red[tid] = fmaxf(red[tid], red[tid + s]);
        __syncthreads();
    }
    float mx = red[0];
    __syncthreads();
    float e = expf(logit - mx);
    p[tid] = e; red[tid] = e; __syncthreads();
    for (int s = 128; s > 0; s >>= 1) {
        if (tid < s) red[tid] += red[tid + s];
        __syncthreads();
    }
    float inv = 1.f / red[0];
    int d = tid & 31, g = tid >> 5;
    float acc = 0.f;
    for (int jj = g * 32; jj < g * 32 + 32; jj++)
        acc += p[jj] * qkv[((size_t)(b * 256 + jj)) * 768 + 512 + h * 32 + d];
    pv[g][d] = acc;
    __syncthreads();
    if (tid < 32) {
        float s = 0.f;
#pragma unroll
        for (int g2 = 0; g2 < 8; g2++) s += pv[g2][tid];
        wv[((size_t)(b * 256 + i)) * 256 + h * 32 + tid] = s * inv;
    }
}

// ---------------- LayerNorm (node path only) ----------------
__global__ __launch_bounds__(256)
void ln_kernel(const float* __restrict__ x, const float* __restrict__ resid,
               const float* __restrict__ g, const float* __restrict__ bb,
               float* __restrict__ out)
{
    __shared__ float s1[256];
    __shared__ float s2[256];
    size_t row = blockIdx.x;
    int t = threadIdx.x;
    float v = x[row * 256 + t] + resid[row * 256 + t];
    s1[t] = v; s2[t] = v * v;
    __syncthreads();
    for (int s = 128; s > 0; s >>= 1) {
        if (t < s) { s1[t] += s1[t + s]; s2[t] += s2[t + s]; }
        __syncthreads();
    }
    float mean = s1[0] * (1.f / 256.f);
    float var  = s2[0] * (1.f / 256.f) - mean * mean;
    float inv  = rsqrtf(var + 1e-5f);
    out[row * 256 + t] = (v - mean) * inv * g[t] + bb[t];
}

__global__ void copy_conds(const float* __restrict__ c, float* __restrict__ o)
{
    o[threadIdx.x] = c[threadIdx.x];
}

// ======================= fused TF32 GEMM, CTA tile 128x256, warp tile 64x64 =======================
// 2-stage cp.async pipeline, K-chunk 64 (256B smem rows; bank-conflict-free XOR swizzle).
// EPI 0: out0 = tf32r(relu(acc+bias)), row length NFULL, col offset n0       (GEMM2 -> HM)
// EPI 1: v = relu(acc+bias)+resid; LN -> out0 = tf32r(LN out)                (GEMM1 -> Tr)
// EPI 2: v = acc+bias+resid;       LN -> out0 (fp32 out_edges)               (GEMM3)
// FUSEA: A computed on the fly: A[m,k] = tf32r(q_i[k]*k_j[k]/16 + edges[m,k])
// smem: [0,1K) bias | [1K,2K) gamma | [2K,3K) beta | [3K,4K) q | 2 stages @4K (96KB each)
#define TG_STG  98304
#define TC_SMEM (4096 + 2*TG_STG)

template<int EPI, bool RELU, bool FUSEA, int KT>
__global__ __launch_bounds__(256)
void tc2_gemm(const float* __restrict__ A, const float* __restrict__ W,
              const float* __restrict__ bias, const float* __restrict__ resid,
              const float* __restrict__ gam, const float* __restrict__ bet,
              float* __restrict__ out0,
              int NFULL, const float* __restrict__ qkv)
{
    extern __shared__ char smc[];
    const uint32_t sb = smem_to_u32(smc);
    const int tid  = threadIdx.x;
    const int w    = tid >> 5;
    const int lane = tid & 31;
    const int g    = lane >> 2;
    const int t4   = lane & 3;
    const int wm   = (w >> 2) * 64;      // 0 or 64
    const int wn   = (w & 3) * 64;       // 0,64,128,192
    const int m0   = blockIdx.y * 128;
    const int n0   = blockIdx.x * 256;

    float* bias_s = (float*)(smc);
    float* gam_s  = (float*)(smc + 1024);
    float* bet_s  = (float*)(smc + 2048);
    float* qs     = (float*)(smc + 3072);

    bias_s[tid] = bias[n0 + tid];
    if (EPI != 0) { gam_s[tid] = gam[tid]; bet_s[tid] = bet[tid]; }
    int bq = 0, jb = 0;
    if (FUSEA) {
        bq = m0 >> 16;
        int ib = (m0 >> 8) & 255;
        jb = m0 & 255;
        qs[tid] = qkv[(size_t)(bq * 256 + ib) * 768 + tid];
    }
    __syncthreads();

    float acc[4][8][4];
#pragma unroll
    for (int mi = 0; mi < 4; mi++)
#pragma unroll
        for (int ni = 0; ni < 8; ni++)
#pragma unroll
            for (int c = 0; c < 4; c++) acc[mi][ni][c] = 0.f;

    // stage layout: A[128][64] (256B rows) then W[256][64]
    auto issueW = [&](int ch, int s) {
        const int k0 = ch * 64;
        const uint32_t sW = sb + 4096 + s * TG_STG + 32768;
#pragma unroll
        for (int i2 = 0; i2 < 16; i2++) {
            int c = tid + i2 * 256;
            int r = c >> 4, kc = (c & 15) * 4;
            cp16(sW + r * 256 + ((kc * 4) ^ ((r & 7) * 16)),
                 W + (size_t)(n0 + r) * KT + k0 + kc);
        }
    };
    auto issueA = [&](int ch, int s) {
        const int k0 = ch * 64;
        const uint32_t sA = sb + 4096 + s * TG_STG;
#pragma unroll
        for (int i2 = 0; i2 < 8; i2++) {
            int c = tid + i2 * 256;
            int r = c >> 4, kc = (c & 15) * 4;
            cp16(sA + r * 256 + ((kc * 4) ^ ((r & 7) * 16)),
                 A + (size_t)(m0 + r) * KT + k0 + kc);
        }
    };
    auto fuseA = [&](int ch, int s) {
        const int k0 = ch * 64;
        char* sA = smc + 4096 + s * TG_STG;
#pragma unroll
        for (int i2 = 0; i2 < 8; i2++) {
            int c = tid + i2 * 256;
            int r = c >> 4, kc = (c & 15) * 4;
            float4 e  = *(const float4*)(A + (size_t)(m0 + r) * 256 + k0 + kc);
            float4 kv = *(const float4*)(qkv + (size_t)(bq * 256 + jb + r) * 768 + 256 + k0 + kc);
            float4 qv = *(const float4*)(qs + k0 + kc);
            float4 v;
            v.x = tf32r(qv.x * kv.x * 0.0625f + e.x);
            v.y = tf32r(qv.y * kv.y * 0.0625f + e.y);
            v.z = tf32r(qv.z * kv.z * 0.0625f + e.z);
            v.w = tf32r(qv.w * kv.w * 0.0625f + e.w);
            *(float4*)(sA + r * 256 + ((kc * 4) ^ ((r & 7) * 16))) = v;
        }
    };

    const int NCH = KT / 64;
    if (!FUSEA) issueA(0, 0);
    issueW(0, 0);
    cp_commit();

    for (int ch = 0; ch < NCH; ch++) {
        const int s = ch & 1;
        if (FUSEA) fuseA(ch, s);
        if (ch + 1 < NCH) {
            if (!FUSEA) issueA(ch + 1, s ^ 1);
            issueW(ch + 1, s ^ 1);
            cp_commit();
            cp_wait<1>();
        } else {
            cp_wait<0>();
        }
        __syncthreads();

        const char* As = smc + 4096 + s * TG_STG;
        const char* Ws = As + 32768;
#pragma unroll
        for (int ks = 0; ks < 8; ks++) {
            const int ka = ks * 8 + t4;
            const int kb = ka + 4;
            uint32_t afr[4][4];
#pragma unroll
            for (int mi = 0; mi < 4; mi++) {
                int r0 = wm + mi * 16 + g, r1 = r0 + 8;
                afr[mi][0] = *(const uint32_t*)(As + r0 * 256 + ((ka * 4) ^ ((r0 & 7) * 16)));
                afr[mi][1] = *(const uint32_t*)(As + r1 * 256 + ((ka * 4) ^ ((r1 & 7) * 16)));
                afr[mi][2] = *(const uint32_t*)(As + r0 * 256 + ((kb * 4) ^ ((r0 & 7) * 16)));
                afr[mi][3] = *(const uint32_t*)(As + r1 * 256 + ((kb * 4) ^ ((r1 & 7) * 16)));
            }
#pragma unroll
            for (int ni = 0; ni < 8; ni++) {
                int nr = wn + ni * 8 + g;
                uint32_t bfr[2];
                bfr[0] = *(const uint32_t*)(Ws + nr * 256 + ((ka * 4) ^ ((nr & 7) * 16)));
                bfr[1] = *(const uint32_t*)(Ws + nr * 256 + ((kb * 4) ^ ((nr & 7) * 16)));
#pragma unroll
                for (int mi = 0; mi < 4; mi++) mma_tf32(acc[mi][ni], afr[mi], bfr);
            }
        }
        __syncthreads();
    }

    // ---------------- epilogue ----------------
    if (EPI == 0) {
#pragma unroll
        for (int mi = 0; mi < 4; mi++)
#pragma unroll
            for (int h = 0; h < 2; h++) {
                int r = m0 + wm + mi * 16 + g + h * 8;
                float* orow = out0 + (size_t)r * NFULL + n0;
#pragma unroll
                for (int ni = 0; ni < 8; ni++) {
                    int col = wn + ni * 8 + t4 * 2;
                    float v0 = acc[mi][ni][h * 2]     + bias_s[col];
                    float v1 = acc[mi][ni][h * 2 + 1] + bias_s[col + 1];
                    if (RELU) { v0 = fmaxf(v0, 0.f); v1 = fmaxf(v1, 0.f); }
                    *(float2*)(orow + col) = make_float2(tf32r(v0), tf32r(v1));
                }
            }
    } else {
        float* rsum = (float*)(smc + 4096);
        float* rsq  = (float*)(smc + 4096 + 2048);
#pragma unroll
        for (int mi = 0; mi < 4; mi++)
#pragma unroll
            for (int h = 0; h < 2; h++) {
                int rl = wm + mi * 16 + g + h * 8;
                const float* rr = resid + (size_t)(m0 + rl) * 256;
                float s = 0.f, q = 0.f;
#pragma unroll
                for (int ni = 0; ni < 8; ni++) {
                    int col = wn + ni * 8 + t4 * 2;
                    float2 rv = *(const float2*)(rr + col);
                    float v0 = acc[mi][ni][h * 2]     + bias_s[col];
                    float v1 = acc[mi][ni][h * 2 + 1] + bias_s[col + 1];
                    if (RELU) { v0 = fmaxf(v0, 0.f); v1 = fmaxf(v1, 0.f); }
                    v0 += rv.x; v1 += rv.y;
                    s += v0 + v1;
                    q += v0 * v0 + v1 * v1;
                }
                s += __shfl_xor_sync(0xFFFFFFFFu, s, 1);
                s += __shfl_xor_sync(0xFFFFFFFFu, s, 2);
                q += __shfl_xor_sync(0xFFFFFFFFu, q, 1);
                q += __shfl_xor_sync(0xFFFFFFFFu, q, 2);
                if (t4 == 0) {
                    rsum[rl * 4 + (w & 3)] = s;
                    rsq [rl * 4 + (w & 3)] = q;
                }
            }
        __syncthreads();
#pragma unroll
        for (int mi = 0; mi < 4; mi++)
#pragma unroll
            for (int h = 0; h < 2; h++) {
                int rl = wm + mi * 16 + g + h * 8;
                float tot = rsum[rl * 4] + rsum[rl * 4 + 1] + rsum[rl * 4 + 2] + rsum[rl * 4 + 3];
                float tq  = rsq [rl * 4] + rsq [rl * 4 + 1] + rsq [rl * 4 + 2] + rsq [rl * 4 + 3];
                float mean = tot * (1.f / 256.f);
                float var  = tq * (1.f / 256.f) - mean * mean;
                float inv  = rsqrtf(var + 1e-5f);
                const float* rr = resid + (size_t)(m0 + rl) * 256;
                size_t orow = (size_t)(m0 + rl) * 256;
#pragma unroll
                for (int ni = 0; ni < 8; ni++) {
                    int col = wn + ni * 8 + t4 * 2;
                    float2 rv = *(const float2*)(rr + col);
                    float v0 = acc[mi][ni][h * 2]     + bias_s[col];
                    float v1 = acc[mi][ni][h * 2 + 1] + bias_s[col + 1];
                    if (RELU) { v0 = fmaxf(v0, 0.f); v1 = fmaxf(v1, 0.f); }
                    v0 += rv.x; v1 += rv.y;
                    float o0 = (v0 - mean) * inv * gam_s[col]     + bet_s[col];
                    float o1 = (v1 - mean) * inv * gam_s[col + 1] + bet_s[col + 1];
                    if (EPI == 1) { o0 = tf32r(o0); o1 = tf32r(o1); }
                    *(float2*)(out0 + orow + col) = make_float2(o0, o1);
                }
            }
    }
}

// ======================= launch =======================
extern "C" void kernel_launch(void* const* d_in, const int* in_sizes, int n_in,
                              void* d_out, int out_size)
{
    const float* nodes = (const float*)d_in[0];
    const float* edges = (const float*)d_in[1];
    const float* conds = (const float*)d_in[2];
    const float* Wqkv  = (const float*)d_in[3];
    const float* bqkv  = (const float*)d_in[4];
    const float* Wno   = (const float*)d_in[5];
    const float* bno   = (const float*)d_in[6];
    const float* Weo   = (const float*)d_in[7];
    const float* beo   = (const float*)d_in[8];
    const float* g1n   = (const float*)d_in[9];
    const float* b1n   = (const float*)d_in[10];
    const float* g1e   = (const float*)d_in[11];
    const float* b1e   = (const float*)d_in[12];
    const float* Wn1   = (const float*)d_in[13];
    const float* bn1   = (const float*)d_in[14];
    const float* Wn2   = (const float*)d_in[15];
    const float* bn2   = (const float*)d_in[16];
    const float* We1   = (const float*)d_in[17];
    const float* be1   = (const float*)d_in[18];
    const float* We2   = (const float*)d_in[19];
    const float* be2   = (const float*)d_in[20];
    const float* g2n   = (const float*)d_in[21];
    const float* b2n   = (const float*)d_in[22];
    const float* g2e   = (const float*)d_in[23];
    const float* b2e   = (const float*)d_in[24];

    float *X, *QKV, *WV, *N1, *NA, *NH, *NO;
    float *Tr, *HM, *Weor, *We1r, *We2r;
    cudaGetSymbolAddress((void**)&X,    g_X);
    cudaGetSymbolAddress((void**)&QKV,  g_qkv);
    cudaGetSymbolAddress((void**)&WV,   g_wv);
    cudaGetSymbolAddress((void**)&N1,   g_n1);
    cudaGetSymbolAddress((void**)&NA,   g_nA);
    cudaGetSymbolAddress((void**)&NH,   g_nh);
    cudaGetSymbolAddress((void**)&NO,   g_no);
    cudaGetSymbolAddress((void**)&Tr,   g_Tr);
    cudaGetSymbolAddress((void**)&HM,   g_Hm);
    cudaGetSymbolAddress((void**)&Weor, g_Weor);
    cudaGetSymbolAddress((void**)&We1r, g_We1r);
    cudaGetSymbolAddress((void**)&We2r, g_We2r);

    float* out_nodes = (float*)d_out;
    float* out_edges = out_nodes + SZ_NODES;
    float* out_conds = out_edges + SZ_EDGES;

    cudaFuncSetAttribute(tc2_gemm<1, true,  true,  256>,
                         cudaFuncAttributeMaxDynamicSharedMemorySize, TC_SMEM);
    cudaFuncSetAttribute(tc2_gemm<0, true,  false, 256>,
                         cudaFuncAttributeMaxDynamicSharedMemorySize, TC_SMEM);
    cudaFuncSetAttribute(tc2_gemm<2, false, false, 1024>,
                         cudaFuncAttributeMaxDynamicSharedMemorySize, TC_SMEM);

    // weight rounding (tiny)
    wround_kernel<<<256,  256>>>(Weo, Weor, 256 * 256);
    wround_kernel<<<1024, 256>>>(We1, We1r, 1024 * 256);
    wround_kernel<<<1024, 256>>>(We2, We2r, 256 * 1024);

    // node/attention path (fp32, small)
    x_kernel<<<512, 256>>>(nodes, conds, X);
    sgemm_kernel<false><<<dim3(6, 4),   256>>>(X,  Wqkv, bqkv, QKV, 512, 768, 256);
    attn_kernel<<<dim3(256, 8, 2), 256>>>(QKV, edges, WV);
    sgemm_kernel<false><<<dim3(2, 4),   256>>>(WV, Wno,  bno,  N1,  512, 256, 256);
    ln_kernel<<<512, 256>>>(N1, nodes, g1n, b1n, NA);
    sgemm_kernel<true ><<<dim3(8, 4),   256>>>(NA, Wn1,  bn1,  NH,  512, 1024, 256);
    sgemm_kernel<false><<<dim3(2, 4),   256>>>(NH, Wn2,  bn2,  NO,  512, 256, 1024);
    ln_kernel<<<512, 256>>>(NO, NA, g2n, b2n, out_nodes);

    // edge path (fused tf32 tensor-core GEMMs, K-chunk 64)
    // GEMM1: build R in-loader, GEMM vs Weo, relu+bias, +edges, LN1 -> Tr (tf32)
    tc2_gemm<1, true, true, 256><<<dim3(1, 1024), 256, TC_SMEM>>>(
        edges, Weor, beo, edges, g1e, b1e, Tr, 256, QKV);
    // GEMM2: HM = tf32r(relu(Tr @ We1^T + be1))
    tc2_gemm<0, true, false, 256><<<dim3(4, 1024), 256, TC_SMEM>>>(
        Tr, We1r, be1, nullptr, nullptr, nullptr, HM, 1024, nullptr);
    // GEMM3: out_edges = LN(HM @ We2^T + be2 + Tr)
    tc2_gemm<2, false, false, 1024><<<dim3(1, 1024), 256, TC_SMEM>>>(
        HM, We2r, be2, Tr, g2e, b2e, out_edges, 256, nullptr);

    copy_conds<<<1, 512>>>(conds, out_conds);
}

// round 13
// speedup vs baseline: 1.5082x; 1.3850x over previous
#include <cuda_runtime.h>
#include <cuda_fp16.h>
#include <math.h>
#include <stdint.h>

// Problem constants
#define Bb 2
#define Nn 256
#define Dd 256
#define Ee 256
#define SZ_NODES (Bb*Nn*Dd)            // 131072
#define SZ_EDGES ((size_t)Bb*Nn*Nn*Ee) // 33554432
#define M_EDGE   (Bb*Nn*Nn)            // 131072

// ======================= helpers =======================
__device__ __forceinline__ uint32_t smem_to_u32(const void* smem_ptr) {
    uint32_t addr;
    asm("{ .reg .u64 tmp; cvta.to.shared.u64 tmp, %1; cvt.u32.u64 %0, tmp; }"
        : "=r"(addr) : "l"(smem_ptr));
    return addr;
}
__device__ __forceinline__ void cp16(uint32_t dst, const void* src) {
    asm volatile("cp.async.cg.shared.global [%0], [%1], 16;" :: "r"(dst), "l"(src));
}
__device__ __forceinline__ void cp_commit() {
    asm volatile("cp.async.commit_group;");
}
template<int NMAX>
__device__ __forceinline__ void cp_wait() {
    asm volatile("cp.async.wait_group %0;" :: "n"(NMAX));
}
// fp16 tensor-core MMA: D(16x8,f32) += A(16x16,f16) * B(16x8,f16)
__device__ __forceinline__ void mma_f16(float* d, const uint32_t* a, const uint32_t* b) {
    asm volatile(
        "mma.sync.aligned.m16n8k16.row.col.f32.f16.f16.f32 "
        "{%0,%1,%2,%3},{%4,%5,%6,%7},{%8,%9},{%0,%1,%2,%3};"
        : "+f"(d[0]), "+f"(d[1]), "+f"(d[2]), "+f"(d[3])
        : "r"(a[0]), "r"(a[1]), "r"(a[2]), "r"(a[3]), "r"(b[0]), "r"(b[1]));
}

// ======================= scratch (static device memory) =======================
__device__ float g_X  [512*256];
__device__ float g_qkv[512*768];
__device__ float g_wv [512*256];
__device__ float g_n1 [512*256];
__device__ float g_nA [512*256];
__device__ float g_nh [512*1024];
__device__ float g_no [512*256];

__device__ __half g_Tr [(size_t)M_EDGE*256];   // fp16 LN1 output
__device__ __half g_Hm [(size_t)M_EDGE*1024];  // fp16 MLP hidden
__device__ __half g_Weoh[256*256];
__device__ __half g_We1h[1024*256];
__device__ __half g_We2h[256*1024];

// ======================= small kernels =======================
__global__ void x_kernel(const float* __restrict__ nodes,
                         const float* __restrict__ conds,
                         float* __restrict__ X)
{
    int idx = blockIdx.x * 256 + threadIdx.x;
    int b = idx >> 16;
    int d = idx & 255;
    X[idx] = nodes[idx] + conds[b * 256 + d];
}

__global__ void whalf_kernel(const float* __restrict__ s, __half* __restrict__ d, int n)
{
    int i = blockIdx.x * 256 + threadIdx.x;
    if (i < n) d[i] = __float2half_rn(s[i]);
}

// ---------------- fp32 SGEMM for the (small) node path ----------------
template<bool RELU>
__global__ __launch_bounds__(256, 2)
void sgemm_kernel(const float* __restrict__ A, const float* __restrict__ W,
                  const float* __restrict__ bias, float* __restrict__ C,
                  int M, int N, int K)
{
    __shared__ float As[16][128];
    __shared__ float Ws[16][128];
    const int tid  = threadIdx.x;
    const int tx   = tid & 15;
    const int ty   = tid >> 4;
    const int lrow = tid >> 2;
    const int lcol = (tid & 3) << 2;
    const float* Ab = A + (size_t)blockIdx.y * 128 * K;
    const float* Wb = W + (size_t)blockIdx.x * 128 * K;
    float acc[8][8];
#pragma unroll
    for (int r = 0; r < 8; r++)
#pragma unroll
        for (int c = 0; c < 8; c++) acc[r][c] = 0.f;
    for (int k0 = 0; k0 < K; k0 += 16) {
        float4 a0 = *(const float4*)(Ab + (size_t)lrow        * K + k0 + lcol);
        float4 a1 = *(const float4*)(Ab + (size_t)(lrow + 64) * K + k0 + lcol);
        float4 w0 = *(const float4*)(Wb + (size_t)lrow        * K + k0 + lcol);
        float4 w1 = *(const float4*)(Wb + (size_t)(lrow + 64) * K + k0 + lcol);
        __syncthreads();
        As[lcol+0][lrow]    = a0.x; As[lcol+1][lrow]    = a0.y;
        As[lcol+2][lrow]    = a0.z; As[lcol+3][lrow]    = a0.w;
        As[lcol+0][lrow+64] = a1.x; As[lcol+1][lrow+64] = a1.y;
        As[lcol+2][lrow+64] = a1.z; As[lcol+3][lrow+64] = a1.w;
        Ws[lcol+0][lrow]    = w0.x; Ws[lcol+1][lrow]    = w0.y;
        Ws[lcol+2][lrow]    = w0.z; Ws[lcol+3][lrow]    = w0.w;
        Ws[lcol+0][lrow+64] = w1.x; Ws[lcol+1][lrow+64] = w1.y;
        Ws[lcol+2][lrow+64] = w1.z; Ws[lcol+3][lrow+64] = w1.w;
        __syncthreads();
#pragma unroll
        for (int kk = 0; kk < 16; kk++) {
            float a[8], wv[8];
            *(float4*)(a)      = *(const float4*)&As[kk][ty * 4];
            *(float4*)(a + 4)  = *(const float4*)&As[kk][64 + ty * 4];
            *(float4*)(wv)     = *(const float4*)&Ws[kk][tx * 4];
            *(float4*)(wv + 4) = *(const float4*)&Ws[kk][64 + tx * 4];
#pragma unroll
            for (int r = 0; r < 8; r++)
#pragma unroll
                for (int c = 0; c < 8; c++) acc[r][c] += a[r] * wv[c];
        }
    }
    float bv[8];
#pragma unroll
    for (int c = 0; c < 8; c++) {
        int n = blockIdx.x * 128 + ((c < 4) ? (tx * 4 + c) : (64 + tx * 4 + (c - 4)));
        bv[c] = bias[n];
    }
#pragma unroll
    for (int r = 0; r < 8; r++) {
        int row = blockIdx.y * 128 + ((r < 4) ? (ty * 4 + r) : (64 + ty * 4 + (r - 4)));
        float4 o0, o1; float v;
        v = acc[r][0] + bv[0]; if (RELU) v = fmaxf(v, 0.f); o0.x = v;
        v = acc[r][1] + bv[1]; if (RELU) v = fmaxf(v, 0.f); o0.y = v;
        v = acc[r][2] + bv[2]; if (RELU) v = fmaxf(v, 0.f); o0.z = v;
        v = acc[r][3] + bv[3]; if (RELU) v = fmaxf(v, 0.f); o0.w = v;
        v = acc[r][4] + bv[4]; if (RELU) v = fmaxf(v, 0.f); o1.x = v;
        v = acc[r][5] + bv[5]; if (RELU) v = fmaxf(v, 0.f); o1.y = v;
        v = acc[r][6] + bv[6]; if (RELU) v = fmaxf(v, 0.f); o1.z = v;
        v = acc[r][7] + bv[7]; if (RELU) v = fmaxf(v, 0.f); o1.w = v;
        float* Crow = C + (size_t)row * N + blockIdx.x * 128;
        *(float4*)(Crow + tx * 4)      = o0;
        *(float4*)(Crow + 64 + tx * 4) = o1;
    }
}

// ---------------- attention ----------------
__global__ __launch_bounds__(256)
void attn_kernel(const float* __restrict__ qkv, const float* __restrict__ edges,
                 float* __restrict__ wv)
{
    int i = blockIdx.x, h = blockIdx.y, b = blockIdx.z;
    __shared__ __align__(16) float q[32];
    __shared__ float p[256];
    __shared__ float red[256];
    __shared__ float pv[8][32];
    int tid = threadIdx.x;
    if (tid < 32) q[tid] = qkv[((size_t)(b * 256 + i)) * 768 + h * 32 + tid];
    __syncthreads();
    int j = tid;
    const float4* k4 = (const float4*)(qkv + ((size_t)(b * 256 + j)) * 768 + 256 + h * 32);
    const float4* e4 = (const float4*)(edges + (((size_t)(b * 256 + i)) * 256 + j) * 256 + h * 32);
    float dot = 0.f, es = 0.f;
#pragma unroll
    for (int d4 = 0; d4 < 8; d4++) {
        float4 kv = k4[d4]; float4 ev = e4[d4];
        float4 qv = *(const float4*)&q[d4 * 4];
        dot += qv.x * kv.x + qv.y * kv.y + qv.z * kv.z + qv.w * kv.w;
        es  += ev.x + ev.y + ev.z + ev.w;
    }
    float logit = dot * 0.0625f + es;
    red[tid] = logit; __syncthreads();
    for (int s = 128; s > 0; s >>= 1) {
        if (tid < s) red[tid] = fmaxf(red[tid], red[tid + s]);
        __syncthreads();
    }
    float mx = red[0];
    __syncthreads();
    float e = expf(logit - mx);
    p[tid] = e; red[tid] = e; __syncthreads();
    for (int s = 128; s > 0; s >>= 1) {
        if (tid < s) red[tid] += red[tid + s];
        __syncthreads();
    }
    float inv = 1.f / red[0];
    int d = tid & 31, g = tid >> 5;
    float acc = 0.f;
    for (int jj = g * 32; jj < g * 32 + 32; jj++)
        acc += p[jj] * qkv[((size_t)(b * 256 + jj)) * 768 + 512 + h * 32 + d];
    pv[g][d] = acc;
    __syncthreads();
    if (tid < 32) {
        float s = 0.f;
#pragma unroll
        for (int g2 = 0; g2 < 8; g2++) s += pv[g2][tid];
        wv[((size_t)(b * 256 + i)) * 256 + h * 32 + tid] = s * inv;
    }
}

// ---------------- LayerNorm (node path only) ----------------
__global__ __launch_bounds__(256)
void ln_kernel(const float* __restrict__ x, const float* __restrict__ resid,
               const float* __restrict__ g, const float* __restrict__ bb,
               float* __restrict__ out)
{
    __shared__ float s1[256];
    __shared__ float s2[256];
    size_t row = blockIdx.x;
    int t = threadIdx.x;
    float v = x[row * 256 + t] + resid[row * 256 + t];
    s1[t] = v; s2[t] = v * v;
    __syncthreads();
    for (int s = 128; s > 0; s >>= 1) {
        if (t < s) { s1[t] += s1[t + s]; s2[t] += s2[t + s]; }
        __syncthreads();
    }
    float mean = s1[0] * (1.f / 256.f);
    float var  = s2[0] * (1.f / 256.f) - mean * mean;
    float inv  = rsqrtf(var + 1e-5f);
    out[row * 256 + t] = (v - mean) * inv * g[t] + bb[t];
}

__global__ void copy_conds(const float* __restrict__ c, float* __restrict__ o)
{
    o[threadIdx.x] = c[threadIdx.x];
}

// ======================= fused FP16 GEMM, CTA tile 128x256, warp tile 64x64 =======================
// mma.sync.m16n8k16.f16 with fp32 accumulators. 2-stage cp.async, K-chunk 128 halves
// (256B smem rows, 16B-XOR swizzle — same bank-safe pattern as the tf32 version).
// EPI 0: outh = half(relu(acc+bias)), row length NFULL, col offset n0       (GEMM2 -> HM)
// EPI 1: v = relu(acc+bias)+residf; LN -> outh = half(LN out)               (GEMM1 -> Tr)
// EPI 2: v = acc+bias+residh;       LN -> outf (fp32 out_edges)             (GEMM3)
// FUSEA: A computed on the fly: A[m,k] = half(q_i[k]*k_j[k]/16 + edges[m,k])
// smem: [0,1K) bias | [1K,2K) gamma | [2K,3K) beta | [3K,4K) q | 2 stages @4K (96KB each)
#define TG_STG  98304
#define TC_SMEM (4096 + 2*TG_STG)

template<int EPI, bool RELU, bool FUSEA, int KT>
__global__ __launch_bounds__(256)
void tch_gemm(const __half* __restrict__ A, const __half* __restrict__ W,
              const float* __restrict__ bias,
              const float* __restrict__ residf, const __half* __restrict__ residh,
              const float* __restrict__ gam, const float* __restrict__ bet,
              __half* __restrict__ outh, float* __restrict__ outf,
              int NFULL, const float* __restrict__ qkv, const float* __restrict__ edges)
{
    extern __shared__ char smc[];
    const uint32_t sb = smem_to_u32(smc);
    const int tid  = threadIdx.x;
    const int w    = tid >> 5;
    const int lane = tid & 31;
    const int g    = lane >> 2;
    const int t4   = lane & 3;
    const int wm   = (w >> 2) * 64;      // 0 or 64
    const int wn   = (w & 3) * 64;       // 0,64,128,192
    const int m0   = blockIdx.y * 128;
    const int n0   = blockIdx.x * 256;

    float* bias_s = (float*)(smc);
    float* gam_s  = (float*)(smc + 1024);
    float* bet_s  = (float*)(smc + 2048);
    float* qs     = (float*)(smc + 3072);

    bias_s[tid] = bias[n0 + tid];
    if (EPI != 0) { gam_s[tid] = gam[tid]; bet_s[tid] = bet[tid]; }
    int bq = 0, jb = 0;
    if (FUSEA) {
        bq = m0 >> 16;
        int ib = (m0 >> 8) & 255;
        jb = m0 & 255;
        qs[tid] = qkv[(size_t)(bq * 256 + ib) * 768 + tid];
    }
    __syncthreads();

    float acc[4][8][4];
#pragma unroll
    for (int mi = 0; mi < 4; mi++)
#pragma unroll
        for (int ni = 0; ni < 8; ni++)
#pragma unroll
            for (int c = 0; c < 4; c++) acc[mi][ni][c] = 0.f;

    // stage layout: A[128] rows of 256B (128 halves) then W[256] rows of 256B
    auto issueW = [&](int ch, int s) {
        const int k0 = ch * 128;
        const uint32_t sW = sb + 4096 + s * TG_STG + 32768;
#pragma unroll
        for (int i2 = 0; i2 < 16; i2++) {
            int c = tid + i2 * 256;
            int r = c >> 4, kc = (c & 15) * 8;            // kc in halves
            cp16(sW + r * 256 + ((kc * 2) ^ ((r & 7) * 16)),
                 W + (size_t)(n0 + r) * KT + k0 + kc);
        }
    };
    auto issueA = [&](int ch, int s) {
        const int k0 = ch * 128;
        const uint32_t sA = sb + 4096 + s * TG_STG;
#pragma unroll
        for (int i2 = 0; i2 < 8; i2++) {
            int c = tid + i2 * 256;
            int r = c >> 4, kc = (c & 15) * 8;
            cp16(sA + r * 256 + ((kc * 2) ^ ((r & 7) * 16)),
                 A + (size_t)(m0 + r) * KT + k0 + kc);
        }
    };
    auto fuseA = [&](int ch, int s) {
        const int k0 = ch * 128;
        char* sA = smc + 4096 + s * TG_STG;
#pragma unroll
        for (int i2 = 0; i2 < 8; i2++) {
            int c = tid + i2 * 256;
            int r = c >> 4, kc = (c & 15) * 8;
            const float* ep = edges + (size_t)(m0 + r) * 256 + k0 + kc;
            const float* kp = qkv + (size_t)(bq * 256 + jb + r) * 768 + 256 + k0 + kc;
            const float* qp = qs + k0 + kc;
            __half hv[8];
#pragma unroll
            for (int q8 = 0; q8 < 2; q8++) {
                float4 e  = *(const float4*)(ep + q8 * 4);
                float4 kv = *(const float4*)(kp + q8 * 4);
                float4 qv = *(const float4*)(qp + q8 * 4);
                hv[q8 * 4 + 0] = __float2half_rn(qv.x * kv.x * 0.0625f + e.x);
                hv[q8 * 4 + 1] = __float2half_rn(qv.y * kv.y * 0.0625f + e.y);
                hv[q8 * 4 + 2] = __float2half_rn(qv.z * kv.z * 0.0625f + e.z);
                hv[q8 * 4 + 3] = __float2half_rn(qv.w * kv.w * 0.0625f + e.w);
            }
            *(uint4*)(sA + r * 256 + ((kc * 2) ^ ((r & 7) * 16))) = *(uint4*)hv;
        }
    };

    const int NCH = KT / 128;
    if (!FUSEA) issueA(0, 0);
    issueW(0, 0);
    cp_commit();

    for (int ch = 0; ch < NCH; ch++) {
        const int s = ch & 1;
        if (FUSEA) fuseA(ch, s);
        if (ch + 1 < NCH) {
            if (!FUSEA) issueA(ch + 1, s ^ 1);
            issueW(ch + 1, s ^ 1);
            cp_commit();
            cp_wait<1>();
        } else {
            cp_wait<0>();
        }
        __syncthreads();

        const char* As = smc + 4096 + s * TG_STG;
        const char* Ws = As + 32768;
#pragma unroll
        for (int ks = 0; ks < 8; ks++) {
            const int ka = ks * 32 + t4 * 4;   // byte offset of k-pair (2 halves)
            const int kb = ka + 16;            // +8 halves
            uint32_t afr[4][4];
#pragma unroll
            for (int mi = 0; mi < 4; mi++) {
                int r0 = wm + mi * 16 + g, r1 = r0 + 8;
                afr[mi][0] = *(const uint32_t*)(As + r0 * 256 + (ka ^ ((r0 & 7) * 16)));
                afr[mi][1] = *(const uint32_t*)(As + r1 * 256 + (ka ^ ((r1 & 7) * 16)));
                afr[mi][2] = *(const uint32_t*)(As + r0 * 256 + (kb ^ ((r0 & 7) * 16)));
                afr[mi][3] = *(const uint32_t*)(As + r1 * 256 + (kb ^ ((r1 & 7) * 16)));
            }
#pragma unroll
            for (int ni = 0; ni < 8; ni++) {
                int nr = wn + ni * 8 + g;
                uint32_t bfr[2];
                bfr[0] = *(const uint32_t*)(Ws + nr * 256 + (ka ^ ((nr & 7) * 16)));
                bfr[1] = *(const uint32_t*)(Ws + nr * 256 + (kb ^ ((nr & 7) * 16)));
#pragma unroll
                for (int mi = 0; mi < 4; mi++) mma_f16(acc[mi][ni], afr[mi], bfr);
            }
        }
        __syncthreads();
    }

    // ---------------- epilogue ----------------
    if (EPI == 0) {
#pragma unroll
        for (int mi = 0; mi < 4; mi++)
#pragma unroll
            for (int h = 0; h < 2; h++) {
                int r = m0 + wm + mi * 16 + g + h * 8;
                __half* orow = outh + (size_t)r * NFULL + n0;
#pragma unroll
                for (int ni = 0; ni < 8; ni++) {
                    int col = wn + ni * 8 + t4 * 2;
                    float v0 = acc[mi][ni][h * 2]     + bias_s[col];
                    float v1 = acc[mi][ni][h * 2 + 1] + bias_s[col + 1];
                    if (RELU) { v0 = fmaxf(v0, 0.f); v1 = fmaxf(v1, 0.f); }
                    *(__half2*)(orow + col) =
                        __halves2half2(__float2half_rn(v0), __float2half_rn(v1));
                }
            }
    } else {
        float* rsum = (float*)(smc + 4096);
        float* rsq  = (float*)(smc + 4096 + 2048);
#pragma unroll
        for (int mi = 0; mi < 4; mi++)
#pragma unroll
            for (int h = 0; h < 2; h++) {
                int rl = wm + mi * 16 + g + h * 8;
                float s = 0.f, q = 0.f;
#pragma unroll
                for (int ni = 0; ni < 8; ni++) {
                    int col = wn + ni * 8 + t4 * 2;
                    float2 rv;
                    if (EPI == 1) {
                        rv = *(const float2*)(residf + (size_t)(m0 + rl) * 256 + col);
                    } else {
                        rv = __half22float2(*(const __half2*)(residh + (size_t)(m0 + rl) * 256 + col));
                    }
                    float v0 = acc[mi][ni][h * 2]     + bias_s[col];
                    float v1 = acc[mi][ni][h * 2 + 1] + bias_s[col + 1];
                    if (RELU) { v0 = fmaxf(v0, 0.f); v1 = fmaxf(v1, 0.f); }
                    v0 += rv.x; v1 += rv.y;
                    s += v0 + v1;
                    q += v0 * v0 + v1 * v1;
                }
                s += __shfl_xor_sync(0xFFFFFFFFu, s, 1);
                s += __shfl_xor_sync(0xFFFFFFFFu, s, 2);
                q += __shfl_xor_sync(0xFFFFFFFFu, q, 1);
                q += __shfl_xor_sync(0xFFFFFFFFu, q, 2);
                if (t4 == 0) {
                    rsum[rl * 4 + (w & 3)] = s;
                    rsq [rl * 4 + (w & 3)] = q;
                }
            }
        __syncthreads();
#pragma unroll
        for (int mi = 0; mi < 4; mi++)
#pragma unroll
            for (int h = 0; h < 2; h++) {
                int rl = wm + mi * 16 + g + h * 8;
                float tot = rsum[rl * 4] + rsum[rl * 4 + 1] + rsum[rl * 4 + 2] + rsum[rl * 4 + 3];
                float tq  = rsq [rl * 4] + rsq [rl * 4 + 1] + rsq [rl * 4 + 2] + rsq [rl * 4 + 3];
                float mean = tot * (1.f / 256.f);
                float var  = tq * (1.f / 256.f) - mean * mean;
                float inv  = rsqrtf(var + 1e-5f);
                size_t orow = (size_t)(m0 + rl) * 256;
#pragma unroll
                for (int ni = 0; ni < 8; ni++) {
                    int col = wn + ni * 8 + t4 * 2;
                    float2 rv;
                    if (EPI == 1) {
                        rv = *(const float2*)(residf + orow + col);
                    } else {
                        rv = __half22float2(*(const __half2*)(residh + orow + col));
                    }
                    float v0 = acc[mi][ni][h * 2]     + bias_s[col];
                    float v1 = acc[mi][ni][h * 2 + 1] + bias_s[col + 1];
                    if (RELU) { v0 = fmaxf(v0, 0.f); v1 = fmaxf(v1, 0.f); }
                    v0 += rv.x; v1 += rv.y;
                    float o0 = (v0 - mean) * inv * gam_s[col]     + bet_s[col];
                    float o1 = (v1 - mean) * inv * gam_s[col + 1] + bet_s[col + 1];
                    if (EPI == 1) {
                        *(__half2*)(outh + orow + col) =
                            __halves2half2(__float2half_rn(o0), __float2half_rn(o1));
                    } else {
                        *(float2*)(outf + orow + col) = make_float2(o0, o1);
                    }
                }
            }
    }
}

// ======================= launch =======================
extern "C" void kernel_launch(void* const* d_in, const int* in_sizes, int n_in,
                              void* d_out, int out_size)
{
    const float* nodes = (const float*)d_in[0];
    const float* edges = (const float*)d_in[1];
    const float* conds = (const float*)d_in[2];
    const float* Wqkv  = (const float*)d_in[3];
    const float* bqkv  = (const float*)d_in[4];
    const float* Wno   = (const float*)d_in[5];
    const float* bno   = (const float*)d_in[6];
    const float* Weo   = (const float*)d_in[7];
    const float* beo   = (const float*)d_in[8];
    const float* g1n   = (const float*)d_in[9];
    const float* b1n   = (const float*)d_in[10];
    const float* g1e   = (const float*)d_in[11];
    const float* b1e   = (const float*)d_in[12];
    const float* Wn1   = (const float*)d_in[13];
    const float* bn1   = (const float*)d_in[14];
    const float* Wn2   = (const float*)d_in[15];
    const float* bn2   = (const float*)d_in[16];
    const float* We1   = (const float*)d_in[17];
    const float* be1   = (const float*)d_in[18];
    const float* We2   = (const float*)d_in[19];
    const float* be2   = (const float*)d_in[20];
    const float* g2n   = (const float*)d_in[21];
    const float* b2n   = (const float*)d_in[22];
    const float* g2e   = (const float*)d_in[23];
    const float* b2e   = (const float*)d_in[24];

    float *X, *QKV, *WV, *N1, *NA, *NH, *NO;
    __half *Tr, *HM, *Weoh, *We1h, *We2h;
    cudaGetSymbolAddress((void**)&X,    g_X);
    cudaGetSymbolAddress((void**)&QKV,  g_qkv);
    cudaGetSymbolAddress((void**)&WV,   g_wv);
    cudaGetSymbolAddress((void**)&N1,   g_n1);
    cudaGetSymbolAddress((void**)&NA,   g_nA);
    cudaGetSymbolAddress((void**)&NH,   g_nh);
    cudaGetSymbolAddress((void**)&NO,   g_no);
    cudaGetSymbolAddress((void**)&Tr,   g_Tr);
    cudaGetSymbolAddress((void**)&HM,   g_Hm);
    cudaGetSymbolAddress((void**)&Weoh, g_Weoh);
    cudaGetSymbolAddress((void**)&We1h, g_We1h);
    cudaGetSymbolAddress((void**)&We2h, g_We2h);

    float* out_nodes = (float*)d_out;
    float* out_edges = out_nodes + SZ_NODES;
    float* out_conds = out_edges + SZ_EDGES;

    cudaFuncSetAttribute(tch_gemm<1, true,  true,  256>,
                         cudaFuncAttributeMaxDynamicSharedMemorySize, TC_SMEM);
    cudaFuncSetAttribute(tch_gemm<0, true,  false, 256>,
                         cudaFuncAttributeMaxDynamicSharedMemorySize, TC_SMEM);
    cudaFuncSetAttribute(tch_gemm<2, false, false, 1024>,
                         cudaFuncAttributeMaxDynamicSharedMemorySize, TC_SMEM);

    // weight conversion (tiny)
    whalf_kernel<<<256,  256>>>(Weo, Weoh, 256 * 256);
    whalf_kernel<<<1024, 256>>>(We1, We1h, 1024 * 256);
    whalf_kernel<<<1024, 256>>>(We2, We2h, 256 * 1024);

    // node/attention path (fp32, small)
    x_kernel<<<512, 256>>>(nodes, conds, X);
    sgemm_kernel<false><<<dim3(6, 4),   256>>>(X,  Wqkv, bqkv, QKV, 512, 768, 256);
    attn_kernel<<<dim3(256, 8, 2), 256>>>(QKV, edges, WV);
    sgemm_kernel<false><<<dim3(2, 4),   256>>>(WV, Wno,  bno,  N1,  512, 256, 256);
    ln_kernel<<<512, 256>>>(N1, nodes, g1n, b1n, NA);
    sgemm_kernel<true ><<<dim3(8, 4),   256>>>(NA, Wn1,  bn1,  NH,  512, 1024, 256);
    sgemm_kernel<false><<<dim3(2, 4),   256>>>(NH, Wn2,  bn2,  NO,  512, 256, 1024);
    ln_kernel<<<512, 256>>>(NO, NA, g2n, b2n, out_nodes);

    // edge path (fp16 tensor-core GEMMs)
    // GEMM1: build R in-loader (fp16), GEMM vs Weo, relu+bias, +edges, LN1 -> Tr (fp16)
    tch_gemm<1, true, true, 256><<<dim3(1, 1024), 256, TC_SMEM>>>(
        nullptr, Weoh, beo, edges, nullptr, g1e, b1e, Tr, nullptr, 256, QKV, edges);
    // GEMM2: HM = half(relu(Tr @ We1^T + be1))
    tch_gemm<0, true, false, 256><<<dim3(4, 1024), 256, TC_SMEM>>>(
        Tr, We1h, be1, nullptr, nullptr, nullptr, nullptr, HM, nullptr, 1024, nullptr, nullptr);
    // GEMM3: out_edges = LN(HM @ We2^T + be2 + Tr)
    tch_gemm<2, false, false, 1024><<<dim3(1, 1024), 256, TC_SMEM>>>(
        HM, We2h, be2, nullptr, Tr, g2e, b2e, nullptr, out_edges, 256, nullptr, nullptr);

    copy_conds<<<1, 512>>>(conds, out_conds);
}

// round 14
// speedup vs baseline: 1.6984x; 1.1262x over previous
#include <cuda_runtime.h>
#include <cuda_fp16.h>
#include <math.h>
#include <stdint.h>

// Problem constants
#define Bb 2
#define Nn 256
#define Dd 256
#define Ee 256
#define SZ_NODES (Bb*Nn*Dd)            // 131072
#define SZ_EDGES ((size_t)Bb*Nn*Nn*Ee) // 33554432
#define M_EDGE   (Bb*Nn*Nn)            // 131072

// ======================= helpers =======================
__device__ __forceinline__ uint32_t smem_to_u32(const void* smem_ptr) {
    uint32_t addr;
    asm("{ .reg .u64 tmp; cvta.to.shared.u64 tmp, %1; cvt.u32.u64 %0, tmp; }"
        : "=r"(addr) : "l"(smem_ptr));
    return addr;
}
__device__ __forceinline__ void cp16(uint32_t dst, const void* src) {
    asm volatile("cp.async.cg.shared.global [%0], [%1], 16;" :: "r"(dst), "l"(src));
}
__device__ __forceinline__ void cp_commit() {
    asm volatile("cp.async.commit_group;");
}
template<int NMAX>
__device__ __forceinline__ void cp_wait() {
    asm volatile("cp.async.wait_group %0;" :: "n"(NMAX));
}
// fp16 tensor-core MMA: D(16x8,f32) += A(16x16,f16) * B(16x8,f16)
__device__ __forceinline__ void mma_f16(float* d, const uint32_t* a, const uint32_t* b) {
    asm volatile(
        "mma.sync.aligned.m16n8k16.row.col.f32.f16.f16.f32 "
        "{%0,%1,%2,%3},{%4,%5,%6,%7},{%8,%9},{%0,%1,%2,%3};"
        : "+f"(d[0]), "+f"(d[1]), "+f"(d[2]), "+f"(d[3])
        : "r"(a[0]), "r"(a[1]), "r"(a[2]), "r"(a[3]), "r"(b[0]), "r"(b[1]));
}

// ======================= scratch (static device memory) =======================
__device__ float g_X  [512*256];
__device__ float g_qkv[512*768];
__device__ float g_wv [512*256];
__device__ float g_n1 [512*256];
__device__ float g_nA [512*256];
__device__ float g_nh [512*1024];
__device__ float g_no [512*256];

__device__ __half g_Tr [(size_t)M_EDGE*256];   // fp16 LN1 output
__device__ __half g_Hm [(size_t)M_EDGE*1024];  // fp16 MLP hidden
__device__ __half g_Weoh[256*256];
__device__ __half g_We1h[1024*256];
__device__ __half g_We2h[256*1024];

// ======================= small kernels =======================
__global__ void x_kernel(const float* __restrict__ nodes,
                         const float* __restrict__ conds,
                         float* __restrict__ X)
{
    int idx = blockIdx.x * 256 + threadIdx.x;
    int b = idx >> 16;
    int d = idx & 255;
    X[idx] = nodes[idx] + conds[b * 256 + d];
}

__global__ void whalf_kernel(const float* __restrict__ s, __half* __restrict__ d, int n)
{
    int i = blockIdx.x * 256 + threadIdx.x;
    if (i < n) d[i] = __float2half_rn(s[i]);
}

// ---------------- fp32 SGEMM for the (small) node path, tile BMx128 ----------------
template<bool RELU, int BM>
__global__ __launch_bounds__(256, 2)
void sgemm_kernel(const float* __restrict__ A, const float* __restrict__ W,
                  const float* __restrict__ bias, float* __restrict__ C,
                  int M, int N, int K)
{
    __shared__ float As[16][BM];
    __shared__ float Ws[16][128];
    const int tid  = threadIdx.x;
    const int tx   = tid & 15;
    const int ty   = tid >> 4;
    const int lrow = tid >> 2;
    const int lcol = (tid & 3) << 2;
    const float* Ab = A + (size_t)blockIdx.y * BM * K;
    const float* Wb = W + (size_t)blockIdx.x * 128 * K;
    constexpr int RPT = BM / 16;   // rows per thread: 8 (BM=128) or 4 (BM=64)
    float acc[RPT][8];
#pragma unroll
    for (int r = 0; r < RPT; r++)
#pragma unroll
        for (int c = 0; c < 8; c++) acc[r][c] = 0.f;
    for (int k0 = 0; k0 < K; k0 += 16) {
        float4 a0 = *(const float4*)(Ab + (size_t)lrow * K + k0 + lcol);
        float4 a1;
        if (BM == 128)
            a1 = *(const float4*)(Ab + (size_t)(lrow + 64) * K + k0 + lcol);
        float4 w0 = *(const float4*)(Wb + (size_t)lrow        * K + k0 + lcol);
        float4 w1 = *(const float4*)(Wb + (size_t)(lrow + 64) * K + k0 + lcol);
        __syncthreads();
        if (BM == 128) {
            As[lcol+0][lrow]    = a0.x; As[lcol+1][lrow]    = a0.y;
            As[lcol+2][lrow]    = a0.z; As[lcol+3][lrow]    = a0.w;
            As[lcol+0][lrow+64] = a1.x; As[lcol+1][lrow+64] = a1.y;
            As[lcol+2][lrow+64] = a1.z; As[lcol+3][lrow+64] = a1.w;
        } else {
            if (tid < BM * 4) {
                As[lcol+0][lrow] = a0.x; As[lcol+1][lrow] = a0.y;
                As[lcol+2][lrow] = a0.z; As[lcol+3][lrow] = a0.w;
            }
        }
        Ws[lcol+0][lrow]    = w0.x; Ws[lcol+1][lrow]    = w0.y;
        Ws[lcol+2][lrow]    = w0.z; Ws[lcol+3][lrow]    = w0.w;
        Ws[lcol+0][lrow+64] = w1.x; Ws[lcol+1][lrow+64] = w1.y;
        Ws[lcol+2][lrow+64] = w1.z; Ws[lcol+3][lrow+64] = w1.w;
        __syncthreads();
#pragma unroll
        for (int kk = 0; kk < 16; kk++) {
            float a[RPT], wv[8];
            *(float4*)(a) = *(const float4*)&As[kk][ty * 4];
            if (BM == 128)
                *(float4*)(a + 4) = *(const float4*)&As[kk][64 + ty * 4];
            *(float4*)(wv)     = *(const float4*)&Ws[kk][tx * 4];
            *(float4*)(wv + 4) = *(const float4*)&Ws[kk][64 + tx * 4];
#pragma unroll
            for (int r = 0; r < RPT; r++)
#pragma unroll
                for (int c = 0; c < 8; c++) acc[r][c] += a[r] * wv[c];
        }
    }
    float bv[8];
#pragma unroll
    for (int c = 0; c < 8; c++) {
        int n = blockIdx.x * 128 + ((c < 4) ? (tx * 4 + c) : (64 + tx * 4 + (c - 4)));
        bv[c] = bias[n];
    }
#pragma unroll
    for (int r = 0; r < RPT; r++) {
        int row = blockIdx.y * BM + ((r < 4) ? (ty * 4 + r) : (64 + ty * 4 + (r - 4)));
        float4 o0, o1; float v;
        v = acc[r][0] + bv[0]; if (RELU) v = fmaxf(v, 0.f); o0.x = v;
        v = acc[r][1] + bv[1]; if (RELU) v = fmaxf(v, 0.f); o0.y = v;
        v = acc[r][2] + bv[2]; if (RELU) v = fmaxf(v, 0.f); o0.z = v;
        v = acc[r][3] + bv[3]; if (RELU) v = fmaxf(v, 0.f); o0.w = v;
        v = acc[r][4] + bv[4]; if (RELU) v = fmaxf(v, 0.f); o1.x = v;
        v = acc[r][5] + bv[5]; if (RELU) v = fmaxf(v, 0.f); o1.y = v;
        v = acc[r][6] + bv[6]; if (RELU) v = fmaxf(v, 0.f); o1.z = v;
        v = acc[r][7] + bv[7]; if (RELU) v = fmaxf(v, 0.f); o1.w = v;
        float* Crow = C + (size_t)row * N + blockIdx.x * 128;
        *(float4*)(Crow + tx * 4)      = o0;
        *(float4*)(Crow + 64 + tx * 4) = o1;
    }
}

// ---------------- attention ----------------
__global__ __launch_bounds__(256)
void attn_kernel(const float* __restrict__ qkv, const float* __restrict__ edges,
                 float* __restrict__ wv)
{
    int i = blockIdx.x, h = blockIdx.y, b = blockIdx.z;
    __shared__ __align__(16) float q[32];
    __shared__ float p[256];
    __shared__ float red[256];
    __shared__ float pv[8][32];
    int tid = threadIdx.x;
    if (tid < 32) q[tid] = qkv[((size_t)(b * 256 + i)) * 768 + h * 32 + tid];
    __syncthreads();
    int j = tid;
    const float4* k4 = (const float4*)(qkv + ((size_t)(b * 256 + j)) * 768 + 256 + h * 32);
    const float4* e4 = (const float4*)(edges + (((size_t)(b * 256 + i)) * 256 + j) * 256 + h * 32);
    float dot = 0.f, es = 0.f;
#pragma unroll
    for (int d4 = 0; d4 < 8; d4++) {
        float4 kv = k4[d4]; float4 ev = e4[d4];
        float4 qv = *(const float4*)&q[d4 * 4];
        dot += qv.x * kv.x + qv.y * kv.y + qv.z * kv.z + qv.w * kv.w;
        es  += ev.x + ev.y + ev.z + ev.w;
    }
    float logit = dot * 0.0625f + es;
    red[tid] = logit; __syncthreads();
    for (int s = 128; s > 0; s >>= 1) {
        if (tid < s) red[tid] = fmaxf(red[tid], red[tid + s]);
        __syncthreads();
    }
    float mx = red[0];
    __syncthreads();
    float e = expf(logit - mx);
    p[tid] = e; red[tid] = e; __syncthreads();
    for (int s = 128; s > 0; s >>= 1) {
        if (tid < s) red[tid] += red[tid + s];
        __syncthreads();
    }
    float inv = 1.f / red[0];
    int d = tid & 31, g = tid >> 5;
    float acc = 0.f;
    for (int jj = g * 32; jj < g * 32 + 32; jj++)
        acc += p[jj] * qkv[((size_t)(b * 256 + jj)) * 768 + 512 + h * 32 + d];
    pv[g][d] = acc;
    __syncthreads();
    if (tid < 32) {
        float s = 0.f;
#pragma unroll
        for (int g2 = 0; g2 < 8; g2++) s += pv[g2][tid];
        wv[((size_t)(b * 256 + i)) * 256 + h * 32 + tid] = s * inv;
    }
}

// ---------------- LayerNorm (node path only) ----------------
__global__ __launch_bounds__(256)
void ln_kernel(const float* __restrict__ x, const float* __restrict__ resid,
               const float* __restrict__ g, const float* __restrict__ bb,
               float* __restrict__ out)
{
    __shared__ float s1[256];
    __shared__ float s2[256];
    size_t row = blockIdx.x;
    int t = threadIdx.x;
    float v = x[row * 256 + t] + resid[row * 256 + t];
    s1[t] = v; s2[t] = v * v;
    __syncthreads();
    for (int s = 128; s > 0; s >>= 1) {
        if (t < s) { s1[t] += s1[t + s]; s2[t] += s2[t + s]; }
        __syncthreads();
    }
    float mean = s1[0] * (1.f / 256.f);
    float var  = s2[0] * (1.f / 256.f) - mean * mean;
    float inv  = rsqrtf(var + 1e-5f);
    out[row * 256 + t] = (v - mean) * inv * g[t] + bb[t];
}

__global__ void copy_conds(const float* __restrict__ c, float* __restrict__ o)
{
    o[threadIdx.x] = c[threadIdx.x];
}

// ======================= fused FP16 GEMM, CTA tile 128x256, warp tile 64x64 =======================
// mma.sync.m16n8k16.f16 with fp32 accumulators. 2-stage cp.async, K-chunk 128 halves.
// EPI 0: outh = half(relu(acc+bias)), row length NFULL, col offset n0       (GEMM2 -> HM)
// EPI 1: v = relu(acc+bias)+residf; LN -> outh = half(LN out)               (GEMM1 -> Tr)
// EPI 2: v = acc+bias+residh;       LN -> outf (fp32 out_edges)             (GEMM3)
// LN epilogue is single-pass over globals: pass1 folds v into acc, pass2 is register-only.
// FUSEA: A computed on the fly: A[m,k] = half(q_i[k]*k_j[k]/16 + edges[m,k])
#define TG_STG  98304
#define TC_SMEM (4096 + 2*TG_STG)

template<int EPI, bool RELU, bool FUSEA, int KT>
__global__ __launch_bounds__(256)
void tch_gemm(const __half* __restrict__ A, const __half* __restrict__ W,
              const float* __restrict__ bias,
              const float* __restrict__ residf, const __half* __restrict__ residh,
              const float* __restrict__ gam, const float* __restrict__ bet,
              __half* __restrict__ outh, float* __restrict__ outf,
              int NFULL, const float* __restrict__ qkv, const float* __restrict__ edges)
{
    extern __shared__ char smc[];
    const uint32_t sb = smem_to_u32(smc);
    const int tid  = threadIdx.x;
    const int w    = tid >> 5;
    const int lane = tid & 31;
    const int g    = lane >> 2;
    const int t4   = lane & 3;
    const int wm   = (w >> 2) * 64;      // 0 or 64
    const int wn   = (w & 3) * 64;       // 0,64,128,192
    const int m0   = blockIdx.y * 128;
    const int n0   = blockIdx.x * 256;

    float* bias_s = (float*)(smc);
    float* gam_s  = (float*)(smc + 1024);
    float* bet_s  = (float*)(smc + 2048);
    float* qs     = (float*)(smc + 3072);

    bias_s[tid] = bias[n0 + tid];
    if (EPI != 0) { gam_s[tid] = gam[tid]; bet_s[tid] = bet[tid]; }
    int bq = 0, jb = 0;
    if (FUSEA) {
        bq = m0 >> 16;
        int ib = (m0 >> 8) & 255;
        jb = m0 & 255;
        qs[tid] = qkv[(size_t)(bq * 256 + ib) * 768 + tid];
    }
    __syncthreads();

    float acc[4][8][4];
#pragma unroll
    for (int mi = 0; mi < 4; mi++)
#pragma unroll
        for (int ni = 0; ni < 8; ni++)
#pragma unroll
            for (int c = 0; c < 4; c++) acc[mi][ni][c] = 0.f;

    // stage layout: A[128] rows of 256B (128 halves) then W[256] rows of 256B
    auto issueW = [&](int ch, int s) {
        const int k0 = ch * 128;
        const uint32_t sW = sb + 4096 + s * TG_STG + 32768;
#pragma unroll
        for (int i2 = 0; i2 < 16; i2++) {
            int c = tid + i2 * 256;
            int r = c >> 4, kc = (c & 15) * 8;            // kc in halves
            cp16(sW + r * 256 + ((kc * 2) ^ ((r & 7) * 16)),
                 W + (size_t)(n0 + r) * KT + k0 + kc);
        }
    };
    auto issueA = [&](int ch, int s) {
        const int k0 = ch * 128;
        const uint32_t sA = sb + 4096 + s * TG_STG;
#pragma unroll
        for (int i2 = 0; i2 < 8; i2++) {
            int c = tid + i2 * 256;
            int r = c >> 4, kc = (c & 15) * 8;
            cp16(sA + r * 256 + ((kc * 2) ^ ((r & 7) * 16)),
                 A + (size_t)(m0 + r) * KT + k0 + kc);
        }
    };
    auto fuseA = [&](int ch, int s) {
        const int k0 = ch * 128;
        char* sA = smc + 4096 + s * TG_STG;
#pragma unroll
        for (int i2 = 0; i2 < 8; i2++) {
            int c = tid + i2 * 256;
            int r = c >> 4, kc = (c & 15) * 8;
            const float* ep = edges + (size_t)(m0 + r) * 256 + k0 + kc;
            const float* kp = qkv + (size_t)(bq * 256 + jb + r) * 768 + 256 + k0 + kc;
            const float* qp = qs + k0 + kc;
            __half hv[8];
#pragma unroll
            for (int q8 = 0; q8 < 2; q8++) {
                float4 e  = *(const float4*)(ep + q8 * 4);
                float4 kv = *(const float4*)(kp + q8 * 4);
                float4 qv = *(const float4*)(qp + q8 * 4);
                hv[q8 * 4 + 0] = __float2half_rn(qv.x * kv.x * 0.0625f + e.x);
                hv[q8 * 4 + 1] = __float2half_rn(qv.y * kv.y * 0.0625f + e.y);
                hv[q8 * 4 + 2] = __float2half_rn(qv.z * kv.z * 0.0625f + e.z);
                hv[q8 * 4 + 3] = __float2half_rn(qv.w * kv.w * 0.0625f + e.w);
            }
            *(uint4*)(sA + r * 256 + ((kc * 2) ^ ((r & 7) * 16))) = *(uint4*)hv;
        }
    };

    const int NCH = KT / 128;
    if (!FUSEA) issueA(0, 0);
    issueW(0, 0);
    cp_commit();

    for (int ch = 0; ch < NCH; ch++) {
        const int s = ch & 1;
        if (FUSEA) fuseA(ch, s);
        if (ch + 1 < NCH) {
            if (!FUSEA) issueA(ch + 1, s ^ 1);
            issueW(ch + 1, s ^ 1);
            cp_commit();
            cp_wait<1>();
        } else {
            cp_wait<0>();
        }
        __syncthreads();

        const char* As = smc + 4096 + s * TG_STG;
        const char* Ws = As + 32768;
#pragma unroll
        for (int ks = 0; ks < 8; ks++) {
            const int ka = ks * 32 + t4 * 4;   // byte offset of k-pair (2 halves)
            const int kb = ka + 16;            // +8 halves
            uint32_t afr[4][4];
#pragma unroll
            for (int mi = 0; mi < 4; mi++) {
                int r0 = wm + mi * 16 + g, r1 = r0 + 8;
                afr[mi][0] = *(const uint32_t*)(As + r0 * 256 + (ka ^ ((r0 & 7) * 16)));
                afr[mi][1] = *(const uint32_t*)(As + r1 * 256 + (ka ^ ((r1 & 7) * 16)));
                afr[mi][2] = *(const uint32_t*)(As + r0 * 256 + (kb ^ ((r0 & 7) * 16)));
                afr[mi][3] = *(const uint32_t*)(As + r1 * 256 + (kb ^ ((r1 & 7) * 16)));
            }
#pragma unroll
            for (int ni = 0; ni < 8; ni++) {
                int nr = wn + ni * 8 + g;
                uint32_t bfr[2];
                bfr[0] = *(const uint32_t*)(Ws + nr * 256 + (ka ^ ((nr & 7) * 16)));
                bfr[1] = *(const uint32_t*)(Ws + nr * 256 + (kb ^ ((nr & 7) * 16)));
#pragma unroll
                for (int mi = 0; mi < 4; mi++) mma_f16(acc[mi][ni], afr[mi], bfr);
            }
        }
        __syncthreads();
    }

    // ---------------- epilogue ----------------
    if (EPI == 0) {
#pragma unroll
        for (int mi = 0; mi < 4; mi++)
#pragma unroll
            for (int h = 0; h < 2; h++) {
                int r = m0 + wm + mi * 16 + g + h * 8;
                __half* orow = outh + (size_t)r * NFULL + n0;
#pragma unroll
                for (int ni = 0; ni < 8; ni++) {
                    int col = wn + ni * 8 + t4 * 2;
                    float v0 = acc[mi][ni][h * 2]     + bias_s[col];
                    float v1 = acc[mi][ni][h * 2 + 1] + bias_s[col + 1];
                    if (RELU) { v0 = fmaxf(v0, 0.f); v1 = fmaxf(v1, 0.f); }
                    *(__half2*)(orow + col) =
                        __halves2half2(__float2half_rn(v0), __float2half_rn(v1));
                }
            }
    } else {
        float* rsum = (float*)(smc + 4096);
        float* rsq  = (float*)(smc + 4096 + 2048);
        // pass 1: fold bias(+relu)+resid into acc; accumulate LN statistics
#pragma unroll
        for (int mi = 0; mi < 4; mi++)
#pragma unroll
            for (int h = 0; h < 2; h++) {
                int rl = wm + mi * 16 + g + h * 8;
                float s = 0.f, q = 0.f;
#pragma unroll
                for (int ni = 0; ni < 8; ni++) {
                    int col = wn + ni * 8 + t4 * 2;
                    float2 rv;
                    if (EPI == 1) {
                        rv = *(const float2*)(residf + (size_t)(m0 + rl) * 256 + col);
                    } else {
                        rv = __half22float2(*(const __half2*)(residh + (size_t)(m0 + rl) * 256 + col));
                    }
                    float v0 = acc[mi][ni][h * 2]     + bias_s[col];
                    float v1 = acc[mi][ni][h * 2 + 1] + bias_s[col + 1];
                    if (RELU) { v0 = fmaxf(v0, 0.f); v1 = fmaxf(v1, 0.f); }
                    v0 += rv.x; v1 += rv.y;
                    acc[mi][ni][h * 2]     = v0;
                    acc[mi][ni][h * 2 + 1] = v1;
                    s += v0 + v1;
                    q += v0 * v0 + v1 * v1;
                }
                s += __shfl_xor_sync(0xFFFFFFFFu, s, 1);
                s += __shfl_xor_sync(0xFFFFFFFFu, s, 2);
                q += __shfl_xor_sync(0xFFFFFFFFu, q, 1);
                q += __shfl_xor_sync(0xFFFFFFFFu, q, 2);
                if (t4 == 0) {
                    rsum[rl * 4 + (w & 3)] = s;
                    rsq [rl * 4 + (w & 3)] = q;
                }
            }
        __syncthreads();
        // pass 2: register-only LN transform + store
#pragma unroll
        for (int mi = 0; mi < 4; mi++)
#pragma unroll
            for (int h = 0; h < 2; h++) {
                int rl = wm + mi * 16 + g + h * 8;
                float tot = rsum[rl * 4] + rsum[rl * 4 + 1] + rsum[rl * 4 + 2] + rsum[rl * 4 + 3];
                float tq  = rsq [rl * 4] + rsq [rl * 4 + 1] + rsq [rl * 4 + 2] + rsq [rl * 4 + 3];
                float mean = tot * (1.f / 256.f);
                float var  = tq * (1.f / 256.f) - mean * mean;
                float inv  = rsqrtf(var + 1e-5f);
                size_t orow = (size_t)(m0 + rl) * 256;
#pragma unroll
                for (int ni = 0; ni < 8; ni++) {
                    int col = wn + ni * 8 + t4 * 2;
                    float o0 = (acc[mi][ni][h * 2]     - mean) * inv * gam_s[col]     + bet_s[col];
                    float o1 = (acc[mi][ni][h * 2 + 1] - mean) * inv * gam_s[col + 1] + bet_s[col + 1];
                    if (EPI == 1) {
                        *(__half2*)(outh + orow + col) =
                            __halves2half2(__float2half_rn(o0), __float2half_rn(o1));
                    } else {
                        *(float2*)(outf + orow + col) = make_float2(o0, o1);
                    }
                }
            }
    }
}

// ======================= launch =======================
extern "C" void kernel_launch(void* const* d_in, const int* in_sizes, int n_in,
                              void* d_out, int out_size)
{
    const float* nodes = (const float*)d_in[0];
    const float* edges = (const float*)d_in[1];
    const float* conds = (const float*)d_in[2];
    const float* Wqkv  = (const float*)d_in[3];
    const float* bqkv  = (const float*)d_in[4];
    const float* Wno   = (const float*)d_in[5];
    const float* bno   = (const float*)d_in[6];
    const float* Weo   = (const float*)d_in[7];
    const float* beo   = (const float*)d_in[8];
    const float* g1n   = (const float*)d_in[9];
    const float* b1n   = (const float*)d_in[10];
    const float* g1e   = (const float*)d_in[11];
    const float* b1e   = (const float*)d_in[12];
    const float* Wn1   = (const float*)d_in[13];
    const float* bn1   = (const float*)d_in[14];
    const float* Wn2   = (const float*)d_in[15];
    const float* bn2   = (const float*)d_in[16];
    const float* We1   = (const float*)d_in[17];
    const float* be1   = (const float*)d_in[18];
    const float* We2   = (const float*)d_in[19];
    const float* be2   = (const float*)d_in[20];
    const float* g2n   = (const float*)d_in[21];
    const float* b2n   = (const float*)d_in[22];
    const float* g2e   = (const float*)d_in[23];
    const float* b2e   = (const float*)d_in[24];

    float *X, *QKV, *WV, *N1, *NA, *NH, *NO;
    __half *Tr, *HM, *Weoh, *We1h, *We2h;
    cudaGetSymbolAddress((void**)&X,    g_X);
    cudaGetSymbolAddress((void**)&QKV,  g_qkv);
    cudaGetSymbolAddress((void**)&WV,   g_wv);
    cudaGetSymbolAddress((void**)&N1,   g_n1);
    cudaGetSymbolAddress((void**)&NA,   g_nA);
    cudaGetSymbolAddress((void**)&NH,   g_nh);
    cudaGetSymbolAddress((void**)&NO,   g_no);
    cudaGetSymbolAddress((void**)&Tr,   g_Tr);
    cudaGetSymbolAddress((void**)&HM,   g_Hm);
    cudaGetSymbolAddress((void**)&Weoh, g_Weoh);
    cudaGetSymbolAddress((void**)&We1h, g_We1h);
    cudaGetSymbolAddress((void**)&We2h, g_We2h);

    float* out_nodes = (float*)d_out;
    float* out_edges = out_nodes + SZ_NODES;
    float* out_conds = out_edges + SZ_EDGES;

    cudaFuncSetAttribute(tch_gemm<1, true,  true,  256>,
                         cudaFuncAttributeMaxDynamicSharedMemorySize, TC_SMEM);
    cudaFuncSetAttribute(tch_gemm<0, true,  false, 256>,
                         cudaFuncAttributeMaxDynamicSharedMemorySize, TC_SMEM);
    cudaFuncSetAttribute(tch_gemm<2, false, false, 1024>,
                         cudaFuncAttributeMaxDynamicSharedMemorySize, TC_SMEM);

    // weight conversion (tiny)
    whalf_kernel<<<256,  256>>>(Weo, Weoh, 256 * 256);
    whalf_kernel<<<1024, 256>>>(We1, We1h, 1024 * 256);
    whalf_kernel<<<1024, 256>>>(We2, We2h, 256 * 1024);

    // node/attention path (fp32, 64-row tiles for occupancy)
    x_kernel<<<512, 256>>>(nodes, conds, X);
    sgemm_kernel<false, 64><<<dim3(6, 8),  256>>>(X,  Wqkv, bqkv, QKV, 512, 768, 256);
    attn_kernel<<<dim3(256, 8, 2), 256>>>(QKV, edges, WV);
    sgemm_kernel<false, 64><<<dim3(2, 8),  256>>>(WV, Wno,  bno,  N1,  512, 256, 256);
    ln_kernel<<<512, 256>>>(N1, nodes, g1n, b1n, NA);
    sgemm_kernel<true,  64><<<dim3(8, 8),  256>>>(NA, Wn1,  bn1,  NH,  512, 1024, 256);
    sgemm_kernel<false, 64><<<dim3(2, 8),  256>>>(NH, Wn2,  bn2,  NO,  512, 256, 1024);
    ln_kernel<<<512, 256>>>(NO, NA, g2n, b2n, out_nodes);

    // edge path (fp16 tensor-core GEMMs)
    // GEMM1: build R in-loader (fp16), GEMM vs Weo, relu+bias, +edges, LN1 -> Tr (fp16)
    tch_gemm<1, true, true, 256><<<dim3(1, 1024), 256, TC_SMEM>>>(
        nullptr, Weoh, beo, edges, nullptr, g1e, b1e, Tr, nullptr, 256, QKV, edges);
    // GEMM2: HM = half(relu(Tr @ We1^T + be1))
    tch_gemm<0, true, false, 256><<<dim3(4, 1024), 256, TC_SMEM>>>(
        Tr, We1h, be1, nullptr, nullptr, nullptr, nullptr, HM, nullptr, 1024, nullptr, nullptr);
    // GEMM3: out_edges = LN(HM @ We2^T + be2 + Tr)
    tch_gemm<2, false, false, 1024><<<dim3(1, 1024), 256, TC_SMEM>>>(
        HM, We2h, be2, nullptr, Tr, g2e, b2e, nullptr, out_edges, 256, nullptr, nullptr);

    copy_conds<<<1, 512>>>(conds, out_conds);
}

// round 16
// speedup vs baseline: 1.8958x; 1.1162x over previous
#include <cuda_runtime.h>
#include <cuda_fp16.h>
#include <math.h>
#include <stdint.h>

// Problem constants
#define Bb 2
#define Nn 256
#define Dd 256
#define Ee 256
#define SZ_NODES (Bb*Nn*Dd)            // 131072
#define SZ_EDGES ((size_t)Bb*Nn*Nn*Ee) // 33554432
#define M_EDGE   (Bb*Nn*Nn)            // 131072

// ======================= helpers =======================
__device__ __forceinline__ uint32_t smem_to_u32(const void* smem_ptr) {
    uint32_t addr;
    asm("{ .reg .u64 tmp; cvta.to.shared.u64 tmp, %1; cvt.u32.u64 %0, tmp; }"
        : "=r"(addr) : "l"(smem_ptr));
    return addr;
}
__device__ __forceinline__ void cp16(uint32_t dst, const void* src) {
    asm volatile("cp.async.cg.shared.global [%0], [%1], 16;" :: "r"(dst), "l"(src));
}
__device__ __forceinline__ void cp_commit() {
    asm volatile("cp.async.commit_group;");
}
template<int NMAX>
__device__ __forceinline__ void cp_wait() {
    asm volatile("cp.async.wait_group %0;" :: "n"(NMAX));
}
// fp16 tensor-core MMA: D(16x8,f32) += A(16x16,f16) * B(16x8,f16)
__device__ __forceinline__ void mma_f16(float* d, const uint32_t* a, const uint32_t* b) {
    asm volatile(
        "mma.sync.aligned.m16n8k16.row.col.f32.f16.f16.f32 "
        "{%0,%1,%2,%3},{%4,%5,%6,%7},{%8,%9},{%0,%1,%2,%3};"
        : "+f"(d[0]), "+f"(d[1]), "+f"(d[2]), "+f"(d[3])
        : "r"(a[0]), "r"(a[1]), "r"(a[2]), "r"(a[3]), "r"(b[0]), "r"(b[1]));
}

// ======================= scratch (static device memory) =======================
__device__ float  g_qkv[512*768];              // fp32 (feeds attn + edge fuseA)
__device__ __half g_Xh [512*256];
__device__ __half g_wvh[512*256];
__device__ __half g_NAh[512*256];
__device__ __half g_NHh[512*1024];

__device__ __half g_Tr [(size_t)M_EDGE*256];   // fp16 LN1 output (edges)
__device__ __half g_Hm [(size_t)M_EDGE*1024];  // fp16 MLP hidden (edges)
__device__ __half g_Weoh[256*256];
__device__ __half g_We1h[1024*256];
__device__ __half g_We2h[256*1024];
__device__ __half g_Wqkvh[768*256];
__device__ __half g_Wnoh[256*256];
__device__ __half g_Wn1h[1024*256];
__device__ __half g_Wn2h[256*1024];

// ======================= small kernels =======================
__global__ void x_kernel(const float* __restrict__ nodes,
                         const float* __restrict__ conds,
                         __half* __restrict__ X)
{
    int idx = blockIdx.x * 256 + threadIdx.x;
    int b = idx >> 16;
    int d = idx & 255;
    X[idx] = __float2half_rn(nodes[idx] + conds[b * 256 + d]);
}

__global__ void whalf_kernel(const float* __restrict__ s, __half* __restrict__ d, int n)
{
    int i = blockIdx.x * 256 + threadIdx.x;
    if (i < n) d[i] = __float2half_rn(s[i]);
}

// ---------------- attention (fp32 QKV in, fp16 WV out) ----------------
__global__ __launch_bounds__(256)
void attn_kernel(const float* __restrict__ qkv, const float* __restrict__ edges,
                 __half* __restrict__ wv)
{
    int i = blockIdx.x, h = blockIdx.y, b = blockIdx.z;
    __shared__ __align__(16) float q[32];
    __shared__ float p[256];
    __shared__ float red[256];
    __shared__ float pv[8][32];
    int tid = threadIdx.x;
    if (tid < 32) q[tid] = qkv[((size_t)(b * 256 + i)) * 768 + h * 32 + tid];
    __syncthreads();
    int j = tid;
    const float4* k4 = (const float4*)(qkv + ((size_t)(b * 256 + j)) * 768 + 256 + h * 32);
    const float4* e4 = (const float4*)(edges + (((size_t)(b * 256 + i)) * 256 + j) * 256 + h * 32);
    float dot = 0.f, es = 0.f;
#pragma unroll
    for (int d4 = 0; d4 < 8; d4++) {
        float4 kv = k4[d4]; float4 ev = e4[d4];
        float4 qv = *(const float4*)&q[d4 * 4];
        dot += qv.x * kv.x + qv.y * kv.y + qv.z * kv.z + qv.w * kv.w;
        es  += ev.x + ev.y + ev.z + ev.w;
    }
    float logit = dot * 0.0625f + es;
    red[tid] = logit; __syncthreads();
    for (int s = 128; s > 0; s >>= 1) {
        if (tid < s) red[tid] = fmaxf(red[tid], red[tid + s]);
        __syncthreads();
    }
    float mx = red[0];
    __syncthreads();
    float e = expf(logit - mx);
    p[tid] = e; red[tid] = e; __syncthreads();
    for (int s = 128; s > 0; s >>= 1) {
        if (tid < s) red[tid] += red[tid + s];
        __syncthreads();
    }
    float inv = 1.f / red[0];
    int d = tid & 31, g = tid >> 5;
    float acc = 0.f;
    for (int jj = g * 32; jj < g * 32 + 32; jj++)
        acc += p[jj] * qkv[((size_t)(b * 256 + jj)) * 768 + 512 + h * 32 + d];
    pv[g][d] = acc;
    __syncthreads();
    if (tid < 32) {
        float s = 0.f;
#pragma unroll
        for (int g2 = 0; g2 < 8; g2++) s += pv[g2][tid];
        wv[((size_t)(b * 256 + i)) * 256 + h * 32 + tid] = __float2half_rn(s * inv);
    }
}

__global__ void copy_conds(const float* __restrict__ c, float* __restrict__ o)
{
    o[threadIdx.x] = c[threadIdx.x];
}

// ======================= fused FP16 GEMM, CTA tile 128x256, warp tile 64x64 =======================
// mma.sync.m16n8k16.f16 with fp32 accumulators. 2-stage cp.async, K-chunk 128 halves.
// EPI 0: outh = half(relu?(acc+bias)), row length NFULL, col offset n0
// EPI 1: v = relu?(acc+bias)+residf(fp32); LN -> outh = half(LN out)
// EPI 2: v = relu?(acc+bias)+residh(fp16); LN -> outf (fp32)
// EPI 3: outf = acc+bias (fp32 plain), row length NFULL, col offset n0
// LN epilogue: pass1 folds v into acc (single global read), pass2 register-only.
// FUSEA: A computed on the fly: A[m,k] = half(q_i[k]*k_j[k]/16 + edges[m,k])
#define TG_STG  98304
#define TC_SMEM (4096 + 2*TG_STG)

template<int EPI, bool RELU, bool FUSEA, int KT>
__global__ __launch_bounds__(256)
void tch_gemm(const __half* __restrict__ A, const __half* __restrict__ W,
              const float* __restrict__ bias,
              const float* __restrict__ residf, const __half* __restrict__ residh,
              const float* __restrict__ gam, const float* __restrict__ bet,
              __half* __restrict__ outh, float* __restrict__ outf,
              int NFULL, const float* __restrict__ qkv, const float* __restrict__ edges)
{
    extern __shared__ char smc[];
    const uint32_t sb = smem_to_u32(smc);
    const int tid  = threadIdx.x;
    const int w    = tid >> 5;
    const int lane = tid & 31;
    const int g    = lane >> 2;
    const int t4   = lane & 3;
    const int wm   = (w >> 2) * 64;
    const int wn   = (w & 3) * 64;
    const int m0   = blockIdx.y * 128;
    const int n0   = blockIdx.x * 256;

    float* bias_s = (float*)(smc);
    float* gam_s  = (float*)(smc + 1024);
    float* bet_s  = (float*)(smc + 2048);
    float* qs     = (float*)(smc + 3072);

    bias_s[tid] = bias[n0 + tid];
    if (EPI == 1 || EPI == 2) { gam_s[tid] = gam[tid]; bet_s[tid] = bet[tid]; }
    int bq = 0, jb = 0;
    if (FUSEA) {
        bq = m0 >> 16;
        int ib = (m0 >> 8) & 255;
        jb = m0 & 255;
        qs[tid] = qkv[(size_t)(bq * 256 + ib) * 768 + tid];
    }
    __syncthreads();

    float acc[4][8][4];
#pragma unroll
    for (int mi = 0; mi < 4; mi++)
#pragma unroll
        for (int ni = 0; ni < 8; ni++)
#pragma unroll
            for (int c = 0; c < 4; c++) acc[mi][ni][c] = 0.f;

    auto issueW = [&](int ch, int s) {
        const int k0 = ch * 128;
        const uint32_t sW = sb + 4096 + s * TG_STG + 32768;
#pragma unroll
        for (int i2 = 0; i2 < 16; i2++) {
            int c = tid + i2 * 256;
            int r = c >> 4, kc = (c & 15) * 8;
            cp16(sW + r * 256 + ((kc * 2) ^ ((r & 7) * 16)),
                 W + (size_t)(n0 + r) * KT + k0 + kc);
        }
    };
    auto issueA = [&](int ch, int s) {
        const int k0 = ch * 128;
        const uint32_t sA = sb + 4096 + s * TG_STG;
#pragma unroll
        for (int i2 = 0; i2 < 8; i2++) {
            int c = tid + i2 * 256;
            int r = c >> 4, kc = (c & 15) * 8;
            cp16(sA + r * 256 + ((kc * 2) ^ ((r & 7) * 16)),
                 A + (size_t)(m0 + r) * KT + k0 + kc);
        }
    };
    auto fuseA = [&](int ch, int s) {
        const int k0 = ch * 128;
        char* sA = smc + 4096 + s * TG_STG;
#pragma unroll
        for (int i2 = 0; i2 < 8; i2++) {
            int c = tid + i2 * 256;
            int r = c >> 4, kc = (c & 15) * 8;
            const float* ep = edges + (size_t)(m0 + r) * 256 + k0 + kc;
            const float* kp = qkv + (size_t)(bq * 256 + jb + r) * 768 + 256 + k0 + kc;
            const float* qp = qs + k0 + kc;
            __half hv[8];
#pragma unroll
            for (int q8 = 0; q8 < 2; q8++) {
                float4 e  = *(const float4*)(ep + q8 * 4);
                float4 kv = *(const float4*)(kp + q8 * 4);
                float4 qv = *(const float4*)(qp + q8 * 4);
                hv[q8 * 4 + 0] = __float2half_rn(qv.x * kv.x * 0.0625f + e.x);
                hv[q8 * 4 + 1] = __float2half_rn(qv.y * kv.y * 0.0625f + e.y);
                hv[q8 * 4 + 2] = __float2half_rn(qv.z * kv.z * 0.0625f + e.z);
                hv[q8 * 4 + 3] = __float2half_rn(qv.w * kv.w * 0.0625f + e.w);
            }
            *(uint4*)(sA + r * 256 + ((kc * 2) ^ ((r & 7) * 16))) = *(uint4*)hv;
        }
    };

    const int NCH = KT / 128;
    if (!FUSEA) issueA(0, 0);
    issueW(0, 0);
    cp_commit();

    for (int ch = 0; ch < NCH; ch++) {
        const int s = ch & 1;
        if (FUSEA) fuseA(ch, s);
        if (ch + 1 < NCH) {
            if (!FUSEA) issueA(ch + 1, s ^ 1);
            issueW(ch + 1, s ^ 1);
            cp_commit();
            cp_wait<1>();
        } else {
            cp_wait<0>();
        }
        __syncthreads();

        const char* As = smc + 4096 + s * TG_STG;
        const char* Ws = As + 32768;
#pragma unroll
        for (int ks = 0; ks < 8; ks++) {
            const int ka = ks * 32 + t4 * 4;
            const int kb = ka + 16;
            uint32_t afr[4][4];
#pragma unroll
            for (int mi = 0; mi < 4; mi++) {
                int r0 = wm + mi * 16 + g, r1 = r0 + 8;
                afr[mi][0] = *(const uint32_t*)(As + r0 * 256 + (ka ^ ((r0 & 7) * 16)));
                afr[mi][1] = *(const uint32_t*)(As + r1 * 256 + (ka ^ ((r1 & 7) * 16)));
                afr[mi][2] = *(const uint32_t*)(As + r0 * 256 + (kb ^ ((r0 & 7) * 16)));
                afr[mi][3] = *(const uint32_t*)(As + r1 * 256 + (kb ^ ((r1 & 7) * 16)));
            }
#pragma unroll
            for (int ni = 0; ni < 8; ni++) {
                int nr = wn + ni * 8 + g;
                uint32_t bfr[2];
                bfr[0] = *(const uint32_t*)(Ws + nr * 256 + (ka ^ ((nr & 7) * 16)));
                bfr[1] = *(const uint32_t*)(Ws + nr * 256 + (kb ^ ((nr & 7) * 16)));
#pragma unroll
                for (int mi = 0; mi < 4; mi++) mma_f16(acc[mi][ni], afr[mi], bfr);
            }
        }
        __syncthreads();
    }

    // ---------------- epilogue ----------------
    if (EPI == 0 || EPI == 3) {
#pragma unroll
        for (int mi = 0; mi < 4; mi++)
#pragma unroll
            for (int h = 0; h < 2; h++) {
                int r = m0 + wm + mi * 16 + g + h * 8;
#pragma unroll
                for (int ni = 0; ni < 8; ni++) {
                    int col = wn + ni * 8 + t4 * 2;
                    float v0 = acc[mi][ni][h * 2]     + bias_s[col];
                    float v1 = acc[mi][ni][h * 2 + 1] + bias_s[col + 1];
                    if (RELU) { v0 = fmaxf(v0, 0.f); v1 = fmaxf(v1, 0.f); }
                    if (EPI == 0) {
                        *(__half2*)(outh + (size_t)r * NFULL + n0 + col) =
                            __halves2half2(__float2half_rn(v0), __float2half_rn(v1));
                    } else {
                        *(float2*)(outf + (size_t)r * NFULL + n0 + col) = make_float2(v0, v1);
                    }
                }
            }
    } else {
        float* rsum = (float*)(smc + 4096);
        float* rsq  = (float*)(smc + 4096 + 2048);
#pragma unroll
        for (int mi = 0; mi < 4; mi++)
#pragma unroll
            for (int h = 0; h < 2; h++) {
                int rl = wm + mi * 16 + g + h * 8;
                float s = 0.f, q = 0.f;
#pragma unroll
                for (int ni = 0; ni < 8; ni++) {
                    int col = wn + ni * 8 + t4 * 2;
                    float2 rv;
                    if (EPI == 1) {
                        rv = *(const float2*)(residf + (size_t)(m0 + rl) * 256 + col);
                    } else {
                        rv = __half22float2(*(const __half2*)(residh + (size_t)(m0 + rl) * 256 + col));
                    }
                    float v0 = acc[mi][ni][h * 2]     + bias_s[col];
                    float v1 = acc[mi][ni][h * 2 + 1] + bias_s[col + 1];
                    if (RELU) { v0 = fmaxf(v0, 0.f); v1 = fmaxf(v1, 0.f); }
                    v0 += rv.x; v1 += rv.y;
                    acc[mi][ni][h * 2]     = v0;
                    acc[mi][ni][h * 2 + 1] = v1;
                    s += v0 + v1;
                    q += v0 * v0 + v1 * v1;
                }
                s += __shfl_xor_sync(0xFFFFFFFFu, s, 1);
                s += __shfl_xor_sync(0xFFFFFFFFu, s, 2);
                q += __shfl_xor_sync(0xFFFFFFFFu, q, 1);
                q += __shfl_xor_sync(0xFFFFFFFFu, q, 2);
                if (t4 == 0) {
                    rsum[rl * 4 + (w & 3)] = s;
                    rsq [rl * 4 + (w & 3)] = q;
                }
            }
        __syncthreads();
#pragma unroll
        for (int mi = 0; mi < 4; mi++)
#pragma unroll
            for (int h = 0; h < 2; h++) {
                int rl = wm + mi * 16 + g + h * 8;
                float tot = rsum[rl * 4] + rsum[rl * 4 + 1] + rsum[rl * 4 + 2] + rsum[rl * 4 + 3];
                float tq  = rsq [rl * 4] + rsq [rl * 4 + 1] + rsq [rl * 4 + 2] + rsq [rl * 4 + 3];
                float mean = tot * (1.f / 256.f);
                float var  = tq * (1.f / 256.f) - mean * mean;
                float inv  = rsqrtf(var + 1e-5f);
                size_t orow = (size_t)(m0 + rl) * 256;
#pragma unroll
                for (int ni = 0; ni < 8; ni++) {
                    int col = wn + ni * 8 + t4 * 2;
                    float o0 = (acc[mi][ni][h * 2]     - mean) * inv * gam_s[col]     + bet_s[col];
                    float o1 = (acc[mi][ni][h * 2 + 1] - mean) * inv * gam_s[col + 1] + bet_s[col + 1];
                    if (EPI == 1) {
                        *(__half2*)(outh + orow + col) =
                            __halves2half2(__float2half_rn(o0), __float2half_rn(o1));
                    } else {
                        *(float2*)(outf + orow + col) = make_float2(o0, o1);
                    }
                }
            }
    }
}

// ======================= launch =======================
extern "C" void kernel_launch(void* const* d_in, const int* in_sizes, int n_in,
                              void* d_out, int out_size)
{
    const float* nodes = (const float*)d_in[0];
    const float* edges = (const float*)d_in[1];
    const float* conds = (const float*)d_in[2];
    const float* Wqkv  = (const float*)d_in[3];
    const float* bqkv  = (const float*)d_in[4];
    const float* Wno   = (const float*)d_in[5];
    const float* bno   = (const float*)d_in[6];
    const float* Weo   = (const float*)d_in[7];
    const float* beo   = (const float*)d_in[8];
    const float* g1n   = (const float*)d_in[9];
    const float* b1n   = (const float*)d_in[10];
    const float* g1e   = (const float*)d_in[11];
    const float* b1e   = (const float*)d_in[12];
    const float* Wn1   = (const float*)d_in[13];
    const float* bn1   = (const float*)d_in[14];
    const float* Wn2   = (const float*)d_in[15];
    const float* bn2   = (const float*)d_in[16];
    const float* We1   = (const float*)d_in[17];
    const float* be1   = (const float*)d_in[18];
    const float* We2   = (const float*)d_in[19];
    const float* be2   = (const float*)d_in[20];
    const float* g2n   = (const float*)d_in[21];
    const float* b2n   = (const float*)d_in[22];
    const float* g2e   = (const float*)d_in[23];
    const float* b2e   = (const float*)d_in[24];

    float* QKV;
    __half *Xh, *WVh, *NAh, *NHh;
    __half *Tr, *HM, *Weoh, *We1h, *We2h, *Wqkvh, *Wnoh, *Wn1h, *Wn2h;
    cudaGetSymbolAddress((void**)&QKV,   g_qkv);
    cudaGetSymbolAddress((void**)&Xh,    g_Xh);
    cudaGetSymbolAddress((void**)&WVh,   g_wvh);
    cudaGetSymbolAddress((void**)&NAh,   g_NAh);
    cudaGetSymbolAddress((void**)&NHh,   g_NHh);
    cudaGetSymbolAddress((void**)&Tr,    g_Tr);
    cudaGetSymbolAddress((void**)&HM,    g_Hm);
    cudaGetSymbolAddress((void**)&Weoh,  g_Weoh);
    cudaGetSymbolAddress((void**)&We1h,  g_We1h);
    cudaGetSymbolAddress((void**)&We2h,  g_We2h);
    cudaGetSymbolAddress((void**)&Wqkvh, g_Wqkvh);
    cudaGetSymbolAddress((void**)&Wnoh,  g_Wnoh);
    cudaGetSymbolAddress((void**)&Wn1h,  g_Wn1h);
    cudaGetSymbolAddress((void**)&Wn2h,  g_Wn2h);

    float* out_nodes = (float*)d_out;
    float* out_edges = out_nodes + SZ_NODES;
    float* out_conds = out_edges + SZ_EDGES;

    cudaFuncSetAttribute(tch_gemm<3, false, false, 256>,
                         cudaFuncAttributeMaxDynamicSharedMemorySize, TC_SMEM);
    cudaFuncSetAttribute(tch_gemm<1, false, false, 256>,
                         cudaFuncAttributeMaxDynamicSharedMemorySize, TC_SMEM);
    cudaFuncSetAttribute(tch_gemm<1, true,  true,  256>,
                         cudaFuncAttributeMaxDynamicSharedMemorySize, TC_SMEM);
    cudaFuncSetAttribute(tch_gemm<0, true,  false, 256>,
                         cudaFuncAttributeMaxDynamicSharedMemorySize, TC_SMEM);
    cudaFuncSetAttribute(tch_gemm<2, false, false, 1024>,
                         cudaFuncAttributeMaxDynamicSharedMemorySize, TC_SMEM);

    // weight conversion (tiny)
    whalf_kernel<<<768,  256>>>(Wqkv, Wqkvh, 768 * 256);
    whalf_kernel<<<256,  256>>>(Wno,  Wnoh,  256 * 256);
    whalf_kernel<<<1024, 256>>>(Wn1,  Wn1h,  1024 * 256);
    whalf_kernel<<<1024, 256>>>(Wn2,  Wn2h,  256 * 1024);
    whalf_kernel<<<256,  256>>>(Weo,  Weoh,  256 * 256);
    whalf_kernel<<<1024, 256>>>(We1,  We1h,  1024 * 256);
    whalf_kernel<<<1024, 256>>>(We2,  We2h,  256 * 1024);

    // shared prefix: x -> qkv (fp32 out; feeds attn + edge GEMM1 fuseA)
    x_kernel<<<512, 256>>>(nodes, conds, Xh);
    tch_gemm<3, false, false, 256><<<dim3(3, 4), 256, TC_SMEM>>>(
        Xh, Wqkvh, bqkv, nullptr, nullptr, nullptr, nullptr,
        nullptr, QKV, 768, nullptr, nullptr);

    // node path (fp16 tensor cores, LNs fused into GEMM epilogues)
    attn_kernel<<<dim3(256, 8, 2), 256>>>(QKV, edges, WVh);
    tch_gemm<1, false, false, 256><<<dim3(1, 4), 256, TC_SMEM>>>(
        WVh, Wnoh, bno, nodes, nullptr, g1n, b1n,
        NAh, nullptr, 256, nullptr, nullptr);
    tch_gemm<0, true, false, 256><<<dim3(4, 4), 256, TC_SMEM>>>(
        NAh, Wn1h, bn1, nullptr, nullptr, nullptr, nullptr,
        NHh, nullptr, 1024, nullptr, nullptr);
    tch_gemm<2, false, false, 1024><<<dim3(1, 4), 256, TC_SMEM>>>(
        NHh, Wn2h, bn2, nullptr, NAh, g2n, b2n,
        nullptr, out_nodes, 256, nullptr, nullptr);

    // edge path (dominant)
    tch_gemm<1, true, true, 256><<<dim3(1, 1024), 256, TC_SMEM>>>(
        nullptr, Weoh, beo, edges, nullptr, g1e, b1e,
        Tr, nullptr, 256, QKV, edges);
    tch_gemm<0, true, false, 256><<<dim3(4, 1024), 256, TC_SMEM>>>(
        Tr, We1h, be1, nullptr, nullptr, nullptr, nullptr,
        HM, nullptr, 1024, nullptr, nullptr);
    tch_gemm<2, false, false, 1024><<<dim3(1, 1024), 256, TC_SMEM>>>(
        HM, We2h, be2, nullptr, Tr, g2e, b2e,
        nullptr, out_edges, 256, nullptr, nullptr);

    copy_conds<<<1, 512>>>(conds, out_conds);
}

// round 17
// speedup vs baseline: 1.9276x; 1.0168x over previous
#include <cuda_runtime.h>
#include <cuda_fp16.h>
#include <math.h>
#include <stdint.h>

// Problem constants
#define Bb 2
#define Nn 256
#define Dd 256
#define Ee 256
#define SZ_NODES (Bb*Nn*Dd)            // 131072
#define SZ_EDGES ((size_t)Bb*Nn*Nn*Ee) // 33554432
#define M_EDGE   (Bb*Nn*Nn)            // 131072

// ======================= helpers =======================
__device__ __forceinline__ uint32_t smem_to_u32(const void* smem_ptr) {
    uint32_t addr;
    asm("{ .reg .u64 tmp; cvta.to.shared.u64 tmp, %1; cvt.u32.u64 %0, tmp; }"
        : "=r"(addr) : "l"(smem_ptr));
    return addr;
}
__device__ __forceinline__ void cp16(uint32_t dst, const void* src) {
    asm volatile("cp.async.cg.shared.global [%0], [%1], 16;" :: "r"(dst), "l"(src));
}
__device__ __forceinline__ void cp_commit() {
    asm volatile("cp.async.commit_group;");
}
template<int NMAX>
__device__ __forceinline__ void cp_wait() {
    asm volatile("cp.async.wait_group %0;" :: "n"(NMAX));
}
// fp16 tensor-core MMA: D(16x8,f32) += A(16x16,f16) * B(16x8,f16)
__device__ __forceinline__ void mma_f16(float* d, const uint32_t* a, const uint32_t* b) {
    asm volatile(
        "mma.sync.aligned.m16n8k16.row.col.f32.f16.f16.f32 "
        "{%0,%1,%2,%3},{%4,%5,%6,%7},{%8,%9},{%0,%1,%2,%3};"
        : "+f"(d[0]), "+f"(d[1]), "+f"(d[2]), "+f"(d[3])
        : "r"(a[0]), "r"(a[1]), "r"(a[2]), "r"(a[3]), "r"(b[0]), "r"(b[1]));
}
// ldmatrix x4: four 8x8 b16 matrices; lane L supplies row address for its matrix
__device__ __forceinline__ void ldsm4(uint32_t* r, uint32_t addr) {
    asm volatile("ldmatrix.sync.aligned.m8n8.x4.shared.b16 {%0,%1,%2,%3}, [%4];"
        : "=r"(r[0]), "=r"(r[1]), "=r"(r[2]), "=r"(r[3]) : "r"(addr));
}

// ======================= scratch (static device memory) =======================
__device__ float  g_qkv[512*768];              // fp32 (feeds attn + edge fuseA)
__device__ __half g_Xh [512*256];
__device__ __half g_wvh[512*256];
__device__ __half g_NAh[512*256];
__device__ __half g_NHh[512*1024];

__device__ __half g_Tr [(size_t)M_EDGE*256];   // fp16 LN1 output (edges)
__device__ __half g_Hm [(size_t)M_EDGE*1024];  // fp16 MLP hidden (edges)
__device__ __half g_Weoh[256*256];
__device__ __half g_We1h[1024*256];
__device__ __half g_We2h[256*1024];
__device__ __half g_Wqkvh[768*256];
__device__ __half g_Wnoh[256*256];
__device__ __half g_Wn1h[1024*256];
__device__ __half g_Wn2h[256*1024];

// ======================= small kernels =======================
__global__ void x_kernel(const float* __restrict__ nodes,
                         const float* __restrict__ conds,
                         __half* __restrict__ X)
{
    int idx = blockIdx.x * 256 + threadIdx.x;
    int b = idx >> 16;
    int d = idx & 255;
    X[idx] = __float2half_rn(nodes[idx] + conds[b * 256 + d]);
}

// one launch converts all seven weight matrices
__global__ void whalf_all_kernel(
    const float* __restrict__ s0, __half* __restrict__ d0,   // Wqkv 196608
    const float* __restrict__ s1, __half* __restrict__ d1,   // Wno   65536
    const float* __restrict__ s2, __half* __restrict__ d2,   // Wn1  262144
    const float* __restrict__ s3, __half* __restrict__ d3,   // Wn2  262144
    const float* __restrict__ s4, __half* __restrict__ d4,   // Weo   65536
    const float* __restrict__ s5, __half* __restrict__ d5,   // We1  262144
    const float* __restrict__ s6, __half* __restrict__ d6)   // We2  262144
{
    int i = blockIdx.x * 256 + threadIdx.x;  // 0 .. 1376255
    if (i < 196608)       { d0[i] = __float2half_rn(s0[i]); return; }
    i -= 196608;
    if (i < 65536)        { d1[i] = __float2half_rn(s1[i]); return; }
    i -= 65536;
    if (i < 262144)       { d2[i] = __float2half_rn(s2[i]); return; }
    i -= 262144;
    if (i < 262144)       { d3[i] = __float2half_rn(s3[i]); return; }
    i -= 262144;
    if (i < 65536)        { d4[i] = __float2half_rn(s4[i]); return; }
    i -= 65536;
    if (i < 262144)       { d5[i] = __float2half_rn(s5[i]); return; }
    i -= 262144;
    d6[i] = __float2half_rn(s6[i]);
}

// ---------------- attention (fp32 QKV in, fp16 WV out) ----------------
__global__ __launch_bounds__(256)
void attn_kernel(const float* __restrict__ qkv, const float* __restrict__ edges,
                 __half* __restrict__ wv)
{
    int i = blockIdx.x, h = blockIdx.y, b = blockIdx.z;
    __shared__ __align__(16) float q[32];
    __shared__ float p[256];
    __shared__ float red[256];
    __shared__ float pv[8][32];
    int tid = threadIdx.x;
    if (tid < 32) q[tid] = qkv[((size_t)(b * 256 + i)) * 768 + h * 32 + tid];
    __syncthreads();
    int j = tid;
    const float4* k4 = (const float4*)(qkv + ((size_t)(b * 256 + j)) * 768 + 256 + h * 32);
    const float4* e4 = (const float4*)(edges + (((size_t)(b * 256 + i)) * 256 + j) * 256 + h * 32);
    float dot = 0.f, es = 0.f;
#pragma unroll
    for (int d4 = 0; d4 < 8; d4++) {
        float4 kv = k4[d4]; float4 ev = e4[d4];
        float4 qv = *(const float4*)&q[d4 * 4];
        dot += qv.x * kv.x + qv.y * kv.y + qv.z * kv.z + qv.w * kv.w;
        es  += ev.x + ev.y + ev.z + ev.w;
    }
    float logit = dot * 0.0625f + es;
    red[tid] = logit; __syncthreads();
    for (int s = 128; s > 0; s >>= 1) {
        if (tid < s) red[tid] = fmaxf(red[tid], red[tid + s]);
        __syncthreads();
    }
    float mx = red[0];
    __syncthreads();
    float e = expf(logit - mx);
    p[tid] = e; red[tid] = e; __syncthreads();
    for (int s = 128; s > 0; s >>= 1) {
        if (tid < s) red[tid] += red[tid + s];
        __syncthreads();
    }
    float inv = 1.f / red[0];
    int d = tid & 31, g = tid >> 5;
    float acc = 0.f;
    for (int jj = g * 32; jj < g * 32 + 32; jj++)
        acc += p[jj] * qkv[((size_t)(b * 256 + jj)) * 768 + 512 + h * 32 + d];
    pv[g][d] = acc;
    __syncthreads();
    if (tid < 32) {
        float s = 0.f;
#pragma unroll
        for (int g2 = 0; g2 < 8; g2++) s += pv[g2][tid];
        wv[((size_t)(b * 256 + i)) * 256 + h * 32 + tid] = __float2half_rn(s * inv);
    }
}

__global__ void copy_conds(const float* __restrict__ c, float* __restrict__ o)
{
    o[threadIdx.x] = c[threadIdx.x];
}

// ======================= fused FP16 GEMM, CTA tile 128x256, warp tile 64x64 =======================
// mma.sync.m16n8k16.f16 with fp32 accumulators. 2-stage cp.async, K-chunk 128 halves.
// Fragments loaded via ldmatrix.x4 (4x fewer LSU instructions than scalar LDS).
// EPI 0: outh = half(relu?(acc+bias)), row length NFULL, col offset n0
// EPI 1: v = relu?(acc+bias)+residf(fp32); LN -> outh = half(LN out)
// EPI 2: v = relu?(acc+bias)+residh(fp16); LN -> outf (fp32)
// EPI 3: outf = acc+bias (fp32 plain), row length NFULL, col offset n0
// FUSEA: A computed on the fly: A[m,k] = half(q_i[k]*k_j[k]/16 + edges[m,k])
#define TG_STG  98304
#define TC_SMEM (4096 + 2*TG_STG)

template<int EPI, bool RELU, bool FUSEA, int KT>
__global__ __launch_bounds__(256)
void tch_gemm(const __half* __restrict__ A, const __half* __restrict__ W,
              const float* __restrict__ bias,
              const float* __restrict__ residf, const __half* __restrict__ residh,
              const float* __restrict__ gam, const float* __restrict__ bet,
              __half* __restrict__ outh, float* __restrict__ outf,
              int NFULL, const float* __restrict__ qkv, const float* __restrict__ edges)
{
    extern __shared__ char smc[];
    const uint32_t sb = smem_to_u32(smc);
    const int tid  = threadIdx.x;
    const int w    = tid >> 5;
    const int lane = tid & 31;
    const int g    = lane >> 2;
    const int t4   = lane & 3;
    const int wm   = (w >> 2) * 64;
    const int wn   = (w & 3) * 64;
    const int m0   = blockIdx.y * 128;
    const int n0   = blockIdx.x * 256;

    // ldmatrix per-lane addressing components
    const int lane15 = lane & 15;                 // A: row within 16-row block
    const int aHi    = ((lane >> 4) & 1) * 16;    // A: +16B for k8-15 matrices
    const int aswz   = (lane15 & 7) * 16;         // A row swizzle term
    const int bRow   = ((lane >> 4) & 1) * 8 + (lane & 7);  // B: row within 16
    const int bHi    = ((lane >> 3) & 1) * 16;    // B: +16B for b1 matrices
    const int bswz   = (lane & 7) * 16;           // B row swizzle term

    float* bias_s = (float*)(smc);
    float* gam_s  = (float*)(smc + 1024);
    float* bet_s  = (float*)(smc + 2048);
    float* qs     = (float*)(smc + 3072);

    bias_s[tid] = bias[n0 + tid];
    if (EPI == 1 || EPI == 2) { gam_s[tid] = gam[tid]; bet_s[tid] = bet[tid]; }
    int bq = 0, jb = 0;
    if (FUSEA) {
        bq = m0 >> 16;
        int ib = (m0 >> 8) & 255;
        jb = m0 & 255;
        qs[tid] = qkv[(size_t)(bq * 256 + ib) * 768 + tid];
    }
    __syncthreads();

    float acc[4][8][4];
#pragma unroll
    for (int mi = 0; mi < 4; mi++)
#pragma unroll
        for (int ni = 0; ni < 8; ni++)
#pragma unroll
            for (int c = 0; c < 4; c++) acc[mi][ni][c] = 0.f;

    auto issueW = [&](int ch, int s) {
        const int k0 = ch * 128;
        const uint32_t sW = sb + 4096 + s * TG_STG + 32768;
#pragma unroll
        for (int i2 = 0; i2 < 16; i2++) {
            int c = tid + i2 * 256;
            int r = c >> 4, kc = (c & 15) * 8;
            cp16(sW + r * 256 + ((kc * 2) ^ ((r & 7) * 16)),
                 W + (size_t)(n0 + r) * KT + k0 + kc);
        }
    };
    auto issueA = [&](int ch, int s) {
        const int k0 = ch * 128;
        const uint32_t sA = sb + 4096 + s * TG_STG;
#pragma unroll
        for (int i2 = 0; i2 < 8; i2++) {
            int c = tid + i2 * 256;
            int r = c >> 4, kc = (c & 15) * 8;
            cp16(sA + r * 256 + ((kc * 2) ^ ((r & 7) * 16)),
                 A + (size_t)(m0 + r) * KT + k0 + kc);
        }
    };
    auto fuseA = [&](int ch, int s) {
        const int k0 = ch * 128;
        char* sA = smc + 4096 + s * TG_STG;
#pragma unroll
        for (int i2 = 0; i2 < 8; i2++) {
            int c = tid + i2 * 256;
            int r = c >> 4, kc = (c & 15) * 8;
            const float* ep = edges + (size_t)(m0 + r) * 256 + k0 + kc;
            const float* kp = qkv + (size_t)(bq * 256 + jb + r) * 768 + 256 + k0 + kc;
            const float* qp = qs + k0 + kc;
            __half hv[8];
#pragma unroll
            for (int q8 = 0; q8 < 2; q8++) {
                float4 e  = *(const float4*)(ep + q8 * 4);
                float4 kv = *(const float4*)(kp + q8 * 4);
                float4 qv = *(const float4*)(qp + q8 * 4);
                hv[q8 * 4 + 0] = __float2half_rn(qv.x * kv.x * 0.0625f + e.x);
                hv[q8 * 4 + 1] = __float2half_rn(qv.y * kv.y * 0.0625f + e.y);
                hv[q8 * 4 + 2] = __float2half_rn(qv.z * kv.z * 0.0625f + e.z);
                hv[q8 * 4 + 3] = __float2half_rn(qv.w * kv.w * 0.0625f + e.w);
            }
            *(uint4*)(sA + r * 256 + ((kc * 2) ^ ((r & 7) * 16))) = *(uint4*)hv;
        }
    };

    const int NCH = KT / 128;
    if (!FUSEA) issueA(0, 0);
    issueW(0, 0);
    cp_commit();

    for (int ch = 0; ch < NCH; ch++) {
        const int s = ch & 1;
        if (FUSEA) fuseA(ch, s);
        if (ch + 1 < NCH) {
            if (!FUSEA) issueA(ch + 1, s ^ 1);
            issueW(ch + 1, s ^ 1);
            cp_commit();
            cp_wait<1>();
        } else {
            cp_wait<0>();
        }
        __syncthreads();

        const uint32_t sAs = sb + 4096 + s * TG_STG;
        const uint32_t sWs = sAs + 32768;
#pragma unroll
        for (int ks = 0; ks < 8; ks++) {
            uint32_t afr[4][4];
#pragma unroll
            for (int mi = 0; mi < 4; mi++) {
                int row = wm + mi * 16 + lane15;
                ldsm4(afr[mi], sAs + row * 256 + ((ks * 32 + aHi) ^ aswz));
            }
            uint32_t bfr[4][4];
#pragma unroll
            for (int n2 = 0; n2 < 4; n2++) {
                int row = wn + n2 * 16 + bRow;
                ldsm4(bfr[n2], sWs + row * 256 + ((ks * 32 + bHi) ^ bswz));
            }
#pragma unroll
            for (int n2 = 0; n2 < 4; n2++)
#pragma unroll
                for (int mi = 0; mi < 4; mi++) {
                    mma_f16(acc[mi][2 * n2],     afr[mi], &bfr[n2][0]);
                    mma_f16(acc[mi][2 * n2 + 1], afr[mi], &bfr[n2][2]);
                }
        }
        __syncthreads();
    }

    // ---------------- epilogue ----------------
    if (EPI == 0 || EPI == 3) {
#pragma unroll
        for (int mi = 0; mi < 4; mi++)
#pragma unroll
            for (int h = 0; h < 2; h++) {
                int r = m0 + wm + mi * 16 + g + h * 8;
#pragma unroll
                for (int ni = 0; ni < 8; ni++) {
                    int col = wn + ni * 8 + t4 * 2;
                    float v0 = acc[mi][ni][h * 2]     + bias_s[col];
                    float v1 = acc[mi][ni][h * 2 + 1] + bias_s[col + 1];
                    if (RELU) { v0 = fmaxf(v0, 0.f); v1 = fmaxf(v1, 0.f); }
                    if (EPI == 0) {
                        *(__half2*)(outh + (size_t)r * NFULL + n0 + col) =
                            __halves2half2(__float2half_rn(v0), __float2half_rn(v1));
                    } else {
                        *(float2*)(outf + (size_t)r * NFULL + n0 + col) = make_float2(v0, v1);
                    }
                }
            }
    } else {
        float* rsum = (float*)(smc + 4096);
        float* rsq  = (float*)(smc + 4096 + 2048);
#pragma unroll
        for (int mi = 0; mi < 4; mi++)
#pragma unroll
            for (int h = 0; h < 2; h++) {
                int rl = wm + mi * 16 + g + h * 8;
                float s = 0.f, q = 0.f;
#pragma unroll
                for (int ni = 0; ni < 8; ni++) {
                    int col = wn + ni * 8 + t4 * 2;
                    float2 rv;
                    if (EPI == 1) {
                        rv = *(const float2*)(residf + (size_t)(m0 + rl) * 256 + col);
                    } else {
                        rv = __half22float2(*(const __half2*)(residh + (size_t)(m0 + rl) * 256 + col));
                    }
                    float v0 = acc[mi][ni][h * 2]     + bias_s[col];
                    float v1 = acc[mi][ni][h * 2 + 1] + bias_s[col + 1];
                    if (RELU) { v0 = fmaxf(v0, 0.f); v1 = fmaxf(v1, 0.f); }
                    v0 += rv.x; v1 += rv.y;
                    acc[mi][ni][h * 2]     = v0;
                    acc[mi][ni][h * 2 + 1] = v1;
                    s += v0 + v1;
                    q += v0 * v0 + v1 * v1;
                }
                s += __shfl_xor_sync(0xFFFFFFFFu, s, 1);
                s += __shfl_xor_sync(0xFFFFFFFFu, s, 2);
                q += __shfl_xor_sync(0xFFFFFFFFu, q, 1);
                q += __shfl_xor_sync(0xFFFFFFFFu, q, 2);
                if (t4 == 0) {
                    rsum[rl * 4 + (w & 3)] = s;
                    rsq [rl * 4 + (w & 3)] = q;
                }
            }
        __syncthreads();
#pragma unroll
        for (int mi = 0; mi < 4; mi++)
#pragma unroll
            for (int h = 0; h < 2; h++) {
                int rl = wm + mi * 16 + g + h * 8;
                float tot = rsum[rl * 4] + rsum[rl * 4 + 1] + rsum[rl * 4 + 2] + rsum[rl * 4 + 3];
                float tq  = rsq [rl * 4] + rsq [rl * 4 + 1] + rsq [rl * 4 + 2] + rsq [rl * 4 + 3];
                float mean = tot * (1.f / 256.f);
                float var  = tq * (1.f / 256.f) - mean * mean;
                float inv  = rsqrtf(var + 1e-5f);
                size_t orow = (size_t)(m0 + rl) * 256;
#pragma unroll
                for (int ni = 0; ni < 8; ni++) {
                    int col = wn + ni * 8 + t4 * 2;
                    float o0 = (acc[mi][ni][h * 2]     - mean) * inv * gam_s[col]     + bet_s[col];
                    float o1 = (acc[mi][ni][h * 2 + 1] - mean) * inv * gam_s[col + 1] + bet_s[col + 1];
                    if (EPI == 1) {
                        *(__half2*)(outh + orow + col) =
                            __halves2half2(__float2half_rn(o0), __float2half_rn(o1));
                    } else {
                        *(float2*)(outf + orow + col) = make_float2(o0, o1);
                    }
                }
            }
    }
}

// ======================= launch =======================
extern "C" void kernel_launch(void* const* d_in, const int* in_sizes, int n_in,
                              void* d_out, int out_size)
{
    const float* nodes = (const float*)d_in[0];
    const float* edges = (const float*)d_in[1];
    const float* conds = (const float*)d_in[2];
    const float* Wqkv  = (const float*)d_in[3];
    const float* bqkv  = (const float*)d_in[4];
    const float* Wno   = (const float*)d_in[5];
    const float* bno   = (const float*)d_in[6];
    const float* Weo   = (const float*)d_in[7];
    const float* beo   = (const float*)d_in[8];
    const float* g1n   = (const float*)d_in[9];
    const float* b1n   = (const float*)d_in[10];
    const float* g1e   = (const float*)d_in[11];
    const float* b1e   = (const float*)d_in[12];
    const float* Wn1   = (const float*)d_in[13];
    const float* bn1   = (const float*)d_in[14];
    const float* Wn2   = (const float*)d_in[15];
    const float* bn2   = (const float*)d_in[16];
    const float* We1   = (const float*)d_in[17];
    const float* be1   = (const float*)d_in[18];
    const float* We2   = (const float*)d_in[19];
    const float* be2   = (const float*)d_in[20];
    const float* g2n   = (const float*)d_in[21];
    const float* b2n   = (const float*)d_in[22];
    const float* g2e   = (const float*)d_in[23];
    const float* b2e   = (const float*)d_in[24];

    float* QKV;
    __half *Xh, *WVh, *NAh, *NHh;
    __half *Tr, *HM, *Weoh, *We1h, *We2h, *Wqkvh, *Wnoh, *Wn1h, *Wn2h;
    cudaGetSymbolAddress((void**)&QKV,   g_qkv);
    cudaGetSymbolAddress((void**)&Xh,    g_Xh);
    cudaGetSymbolAddress((void**)&WVh,   g_wvh);
    cudaGetSymbolAddress((void**)&NAh,   g_NAh);
    cudaGetSymbolAddress((void**)&NHh,   g_NHh);
    cudaGetSymbolAddress((void**)&Tr,    g_Tr);
    cudaGetSymbolAddress((void**)&HM,    g_Hm);
    cudaGetSymbolAddress((void**)&Weoh,  g_Weoh);
    cudaGetSymbolAddress((void**)&We1h,  g_We1h);
    cudaGetSymbolAddress((void**)&We2h,  g_We2h);
    cudaGetSymbolAddress((void**)&Wqkvh, g_Wqkvh);
    cudaGetSymbolAddress((void**)&Wnoh,  g_Wnoh);
    cudaGetSymbolAddress((void**)&Wn1h,  g_Wn1h);
    cudaGetSymbolAddress((void**)&Wn2h,  g_Wn2h);

    float* out_nodes = (float*)d_out;
    float* out_edges = out_nodes + SZ_NODES;
    float* out_conds = out_edges + SZ_EDGES;

    cudaFuncSetAttribute(tch_gemm<3, false, false, 256>,
                         cudaFuncAttributeMaxDynamicSharedMemorySize, TC_SMEM);
    cudaFuncSetAttribute(tch_gemm<1, false, false, 256>,
                         cudaFuncAttributeMaxDynamicSharedMemorySize, TC_SMEM);
    cudaFuncSetAttribute(tch_gemm<1, true,  true,  256>,
                         cudaFuncAttributeMaxDynamicSharedMemorySize, TC_SMEM);
    cudaFuncSetAttribute(tch_gemm<0, true,  false, 256>,
                         cudaFuncAttributeMaxDynamicSharedMemorySize, TC_SMEM);
    cudaFuncSetAttribute(tch_gemm<2, false, false, 1024>,
                         cudaFuncAttributeMaxDynamicSharedMemorySize, TC_SMEM);

    // all weight conversions in one launch (1376256 elems)
    whalf_all_kernel<<<5376, 256>>>(Wqkv, Wqkvh, Wno, Wnoh, Wn1, Wn1h, Wn2, Wn2h,
                                    Weo, Weoh, We1, We1h, We2, We2h);

    // shared prefix: x -> qkv (fp32 out; feeds attn + edge GEMM1 fuseA)
    x_kernel<<<512, 256>>>(nodes, conds, Xh);
    tch_gemm<3, false, false, 256><<<dim3(3, 4), 256, TC_SMEM>>>(
        Xh, Wqkvh, bqkv, nullptr, nullptr, nullptr, nullptr,
        nullptr, QKV, 768, nullptr, nullptr);

    // node path (fp16 tensor cores, LNs fused into GEMM epilogues)
    attn_kernel<<<dim3(256, 8, 2), 256>>>(QKV, edges, WVh);
    tch_gemm<1, false, false, 256><<<dim3(1, 4), 256, TC_SMEM>>>(
        WVh, Wnoh, bno, nodes, nullptr, g1n, b1n,
        NAh, nullptr, 256, nullptr, nullptr);
    tch_gemm<0, true, false, 256><<<dim3(4, 4), 256, TC_SMEM>>>(
        NAh, Wn1h, bn1, nullptr, nullptr, nullptr, nullptr,
        NHh, nullptr, 1024, nullptr, nullptr);
    tch_gemm<2, false, false, 1024><<<dim3(1, 4), 256, TC_SMEM>>>(
        NHh, Wn2h, bn2, nullptr, NAh, g2n, b2n,
        nullptr, out_nodes, 256, nullptr, nullptr);

    // edge path (dominant)
    tch_gemm<1, true, true, 256><<<dim3(1, 1024), 256, TC_SMEM>>>(
        nullptr, Weoh, beo, edges, nullptr, g1e, b1e,
        Tr, nullptr, 256, QKV, edges);
    tch_gemm<0, true, false, 256><<<dim3(4, 1024), 256, TC_SMEM>>>(
        Tr, We1h, be1, nullptr, nullptr, nullptr, nullptr,
        HM, nullptr, 1024, nullptr, nullptr);
    tch_gemm<2, false, false, 1024><<<dim3(1, 1024), 256, TC_SMEM>>>(
        HM, We2h, be2, nullptr, Tr, g2e, b2e,
        nullptr, out_edges, 256, nullptr, nullptr);

    copy_conds<<<1, 512>>>(conds, out_conds);
}